// round 10
// baseline (speedup 1.0000x reference)
#include <cuda_runtime.h>
#include <math.h>

// Problem constants
#define NT    65536          // N*T rows
#define DD    256            // feature dim
#define MM    512            // codebook size
#define NTD   16777216       // N*T*D

#define ROWS_PER_BLOCK 64
#define NBLOCKS (NT / ROWS_PER_BLOCK)   // 1024
#define CPT    256                      // codes per tile (2 tiles)
#define KC     32                       // k chunk

// smem layout (floats)
#define ES_FLOATS (KC * CPT)            // 8192 floats (32 KB)
#define XD_ULL    66                    // ull per k-row of x_dup (pad)
#define XD_FLOATS (KC * XD_ULL * 2)     // 4224 floats (16.5 KB)
#define SMEM_FLOATS (ES_FLOATS + XD_FLOATS + MM + 64 + 64 + 8 + 8)
#define SMEM_BYTES (SMEM_FLOATS * 4)

// Device scratch
__device__ float g_embnT[DD * MM];      // normalized codebook, transposed [k][j]
__device__ float g_c[MM];               // ||emb_norm_j||^2
__device__ float g_loss_part[NBLOCKS];
__device__ int   g_hist[MM];

// packed fp32x2 FMA (2 IEEE fp32 FMAs per issue)
#define FMA2(d, a, b) asm("fma.rn.f32x2 %0, %1, %2, %0;" : "+l"(d) : "l"(a), "l"(b))
#define UNPK(lo, hi, v) asm("mov.b64 {%0,%1}, %2;" : "=f"(lo), "=f"(hi) : "l"(v))

union F4U { float4 f; unsigned long long u[2]; };

// XLA-style warp reduce over 256 values in shared
__device__ __forceinline__ float warp_reduce256(const float* v, int lane) {
    float s = 0.0f;
#pragma unroll
    for (int c = 0; c < 4; c++) s = __fadd_rn(s, v[4 * lane + c]);
#pragma unroll
    for (int c = 0; c < 4; c++) s = __fadd_rn(s, v[128 + 4 * lane + c]);
#pragma unroll
    for (int off = 16; off > 0; off >>= 1)
        s = __fadd_rn(s, __shfl_xor_sync(0xffffffffu, s, off));
    return s;
}

// ---------------------------------------------------------------------------
// Prep (unchanged from passing round)
// ---------------------------------------------------------------------------
__global__ void vq_prep_kernel(const float* __restrict__ emb) {
    int j = blockIdx.x;
    int t = threadIdx.x;
    __shared__ float sq[256];
    __shared__ float norm_s;

    float v = emb[j * DD + t];
    sq[t] = __fmul_rn(v, v);
    __syncthreads();
    if (t < 32) {
        float s = warp_reduce256(sq, t);
        if (t == 0) norm_s = sqrtf(s);
    }
    __syncthreads();

    float e = v / __fadd_rn(norm_s, 1e-4f);
    g_embnT[t * MM + j] = e;

    sq[t] = __fmul_rn(e, e);
    __syncthreads();
    if (t < 32) {
        float s = warp_reduce256(sq, t);
        if (t == 0) { g_c[j] = s; g_hist[j] = 0; }
    }
}

// ---------------------------------------------------------------------------
// Main: 64 rows x 512 codes per block; FFMA2 inner loop (8 rows x 8 codes/thr)
// ---------------------------------------------------------------------------
__global__ void __launch_bounds__(256, 2)
vq_main_kernel(const float* __restrict__ x,
               const float* __restrict__ emb,
               float* __restrict__ out) {
    extern __shared__ float sm[];
    float* e_s  = sm;                                     // [KC][256]
    unsigned long long* xd = (unsigned long long*)(sm + ES_FLOATS); // [KC][66]
    float* c_s  = sm + ES_FLOATS + XD_FLOATS;             // [512]
    float* sx_s = c_s + MM;                               // [64]
    int*   rowidx = (int*)(sx_s + 64);                    // [64]
    float* lred   = (float*)(rowidx + 64);                // [8]

    const int tid = threadIdx.x;
    const int b   = blockIdx.x;
    const long r0 = (long)b * ROWS_PER_BLOCK;
    const float4* xg4 = (const float4*)(x + r0 * DD);     // row-major, 64 f4/row

    // load c_j
    for (int i = tid; i < MM; i += 256) c_s[i] = g_c[i];

    // sx: per-row ||x||^2 with exact XLA-style rounding/order (from global)
    {
        int w = tid >> 5, l = tid & 31;
#pragma unroll
        for (int rr = 0; rr < 8; rr++) {
            int row = w * 8 + rr;
            float4 a = xg4[row * 64 + l];
            float4 bq = xg4[row * 64 + 32 + l];
            float s = 0.0f;
            s = __fadd_rn(s, __fmul_rn(a.x, a.x));
            s = __fadd_rn(s, __fmul_rn(a.y, a.y));
            s = __fadd_rn(s, __fmul_rn(a.z, a.z));
            s = __fadd_rn(s, __fmul_rn(a.w, a.w));
            s = __fadd_rn(s, __fmul_rn(bq.x, bq.x));
            s = __fadd_rn(s, __fmul_rn(bq.y, bq.y));
            s = __fadd_rn(s, __fmul_rn(bq.z, bq.z));
            s = __fadd_rn(s, __fmul_rn(bq.w, bq.w));
#pragma unroll
            for (int off = 16; off > 0; off >>= 1)
                s = __fadd_rn(s, __shfl_xor_sync(0xffffffffu, s, off));
            if (l == 0) sx_s[row] = s;
        }
    }

    const int tx = tid & 31;   // code group: 8 codes tx*8..tx*8+7 within tile
    const int ty = tid >> 5;   // row group: rows ty*8..ty*8+7

    float bv[8];
    int   bi[8];
#pragma unroll
    for (int i = 0; i < 8; i++) { bv[i] = INFINITY; bi[i] = 0; }

    for (int ct = 0; ct < MM / CPT; ct++) {
        unsigned long long acc[8][4];
#pragma unroll
        for (int i = 0; i < 8; i++)
#pragma unroll
            for (int j = 0; j < 4; j++) acc[i][j] = 0ull;

        for (int kt = 0; kt < DD / KC; kt++) {
            __syncthreads();   // previous chunk users done

            // fill e_s: [KC][256] from g_embnT
#pragma unroll
            for (int i = 0; i < 8; i++) {
                int v4 = tid + i * 256;       // 2048 float4
                int kk = v4 >> 6;
                int jq = v4 & 63;
                float4 val = *(const float4*)&g_embnT[(kt * KC + kk) * MM
                                                      + ct * CPT + jq * 4];
                *(float4*)&e_s[kk * CPT + jq * 4] = val;
            }
            // fill x_dup: rows duplicated, [KC][66 ull]
#pragma unroll
            for (int i = 0; i < 2; i++) {
                int v4  = tid + i * 256;      // 512 float4 (64 rows x 8 kq)
                int row = v4 >> 3;
                int kq  = v4 & 7;
                float4 val = xg4[row * 64 + kt * 8 + kq];
                int k0 = kq * 4;
                F4U p;
                p.f = make_float4(val.x, val.x, val.y, val.y);
                xd[(k0 + 0) * XD_ULL + row] = p.u[0];
                xd[(k0 + 1) * XD_ULL + row] = p.u[1];
                p.f = make_float4(val.z, val.z, val.w, val.w);
                xd[(k0 + 2) * XD_ULL + row] = p.u[0];
                xd[(k0 + 3) * XD_ULL + row] = p.u[1];
            }
            __syncthreads();

#pragma unroll 4
            for (int k = 0; k < KC; k++) {
                const ulonglong2* xp = (const ulonglong2*)&xd[k * XD_ULL + ty * 8];
                ulonglong2 xa = xp[0];  // rows ty*8+0, +1 (dup pairs)
                ulonglong2 xb = xp[1];
                ulonglong2 xc = xp[2];
                ulonglong2 xe = xp[3];
                F4U e0, e1;
                e0.f = *(const float4*)&e_s[k * CPT + tx * 8];
                e1.f = *(const float4*)&e_s[k * CPT + tx * 8 + 4];
                unsigned long long ep0 = e0.u[0], ep1 = e0.u[1];
                unsigned long long ep2 = e1.u[0], ep3 = e1.u[1];

                FMA2(acc[0][0], xa.x, ep0); FMA2(acc[0][1], xa.x, ep1);
                FMA2(acc[0][2], xa.x, ep2); FMA2(acc[0][3], xa.x, ep3);
                FMA2(acc[1][0], xa.y, ep0); FMA2(acc[1][1], xa.y, ep1);
                FMA2(acc[1][2], xa.y, ep2); FMA2(acc[1][3], xa.y, ep3);
                FMA2(acc[2][0], xb.x, ep0); FMA2(acc[2][1], xb.x, ep1);
                FMA2(acc[2][2], xb.x, ep2); FMA2(acc[2][3], xb.x, ep3);
                FMA2(acc[3][0], xb.y, ep0); FMA2(acc[3][1], xb.y, ep1);
                FMA2(acc[3][2], xb.y, ep2); FMA2(acc[3][3], xb.y, ep3);
                FMA2(acc[4][0], xc.x, ep0); FMA2(acc[4][1], xc.x, ep1);
                FMA2(acc[4][2], xc.x, ep2); FMA2(acc[4][3], xc.x, ep3);
                FMA2(acc[5][0], xc.y, ep0); FMA2(acc[5][1], xc.y, ep1);
                FMA2(acc[5][2], xc.y, ep2); FMA2(acc[5][3], xc.y, ep3);
                FMA2(acc[6][0], xe.x, ep0); FMA2(acc[6][1], xe.x, ep1);
                FMA2(acc[6][2], xe.x, ep2); FMA2(acc[6][3], xe.x, ep3);
                FMA2(acc[7][0], xe.y, ep0); FMA2(acc[7][1], xe.y, ep1);
                FMA2(acc[7][2], xe.y, ep2); FMA2(acc[7][3], xe.y, ep3);
            }
        }

        // fold: m = fl( fl(c_j + sx) - 2*s ); strict < keeps lowest index on ties
#pragma unroll
        for (int jp = 0; jp < 4; jp++) {
#pragma unroll
            for (int i = 0; i < 8; i++) {
                float s0, s1;
                UNPK(s0, s1, acc[i][jp]);
                int c0 = ct * CPT + tx * 8 + jp * 2;
                float sx = sx_s[ty * 8 + i];
                float t0 = __fadd_rn(c_s[c0], sx);
                float m0 = __fadd_rn(t0, -2.0f * s0);
                if (m0 < bv[i]) { bv[i] = m0; bi[i] = c0; }
                float t1 = __fadd_rn(c_s[c0 + 1], sx);
                float m1 = __fadd_rn(t1, -2.0f * s1);
                if (m1 < bv[i]) { bv[i] = m1; bi[i] = c0 + 1; }
            }
        }
    }

    // cross-thread argmin reduce, reusing e_s
    __syncthreads();
    float* red_v = e_s;                 // [64][32]
    int*   red_i = (int*)(e_s + 64 * 32);
#pragma unroll
    for (int i = 0; i < 8; i++) {
        int row = ty * 8 + i;
        red_v[row * 32 + tx] = bv[i];
        red_i[row * 32 + tx] = bi[i];
    }
    __syncthreads();
    if (tid < 64) {
        int row = tid;
        float best = red_v[row * 32];
        int   idx  = red_i[row * 32];
        for (int t2 = 1; t2 < 32; t2++) {
            float v = red_v[row * 32 + t2];
            int  ii = red_i[row * 32 + t2];
            if (v < best || (v == best && ii < idx)) { best = v; idx = ii; }
        }
        rowidx[row] = idx;
        atomicAdd(&g_hist[idx], 1);
    }
    __syncthreads();

    // gather codewords; straight-through arithmetic exactly as reference
    float lsum = 0.0f;
    {
        int row   = tid >> 2;
        int kbase = (tid & 3) * 64;
        int idx   = rowidx[row];
        const float4* eq = (const float4*)(emb + (long)idx * DD + kbase);
        const float4* xq = xg4 + row * 64 + (tid & 3) * 16;
        float4*       og = (float4*)(out + (r0 + row) * DD + kbase);
#pragma unroll
        for (int i = 0; i < 16; i++) {
            float4 q  = eq[i];
            float4 xv = xq[i];

            float4 o;
            o.x = __fmul_rn(__fadd_rn(__fadd_rn(xv.x, __fadd_rn(q.x, -xv.x)), q.x), 0.5f);
            o.y = __fmul_rn(__fadd_rn(__fadd_rn(xv.y, __fadd_rn(q.y, -xv.y)), q.y), 0.5f);
            o.z = __fmul_rn(__fadd_rn(__fadd_rn(xv.z, __fadd_rn(q.z, -xv.z)), q.z), 0.5f);
            o.w = __fmul_rn(__fadd_rn(__fadd_rn(xv.w, __fadd_rn(q.w, -xv.w)), q.w), 0.5f);
            og[i] = o;

            float d0 = __fadd_rn(xv.x, -q.x);
            float d1 = __fadd_rn(xv.y, -q.y);
            float d2 = __fadd_rn(xv.z, -q.z);
            float d3 = __fadd_rn(xv.w, -q.w);
            lsum += d0 * d0 + d1 * d1 + d2 * d2 + d3 * d3;
        }
    }
#pragma unroll
    for (int off = 16; off > 0; off >>= 1)
        lsum += __shfl_down_sync(0xffffffffu, lsum, off);
    if ((tid & 31) == 0) lred[tid >> 5] = lsum;
    __syncthreads();
    if (tid == 0) {
        float tot = 0.0f;
        for (int w = 0; w < 8; w++) tot += lred[w];
        g_loss_part[b] = tot;
    }
}

// ---------------------------------------------------------------------------
// Finalize (unchanged)
// ---------------------------------------------------------------------------
__global__ void vq_finalize_kernel(float* __restrict__ out, int write_scalars) {
    __shared__ float red[512];
    int t = threadIdx.x;

    float s = g_loss_part[t] + g_loss_part[t + 512];
    red[t] = s;
    __syncthreads();
#pragma unroll
    for (int st = 256; st > 0; st >>= 1) {
        if (t < st) red[t] += red[t + st];
        __syncthreads();
    }
    float loss = red[0] / (float)NTD;

    float p = (float)g_hist[t] * (1.0f / (float)NT);
    red[t] = p * logf(p + 1e-10f);
    __syncthreads();
#pragma unroll
    for (int st = 256; st > 0; st >>= 1) {
        if (t < st) red[t] += red[t + st];
        __syncthreads();
    }
    if (t == 0 && write_scalars) {
        out[NTD]     = loss;
        out[NTD + 1] = expf(-red[0]);
    }
}

// ---------------------------------------------------------------------------
extern "C" void kernel_launch(void* const* d_in, const int* in_sizes, int n_in,
                              void* d_out, int out_size) {
    const float* x   = (const float*)d_in[0];
    const float* emb = (const float*)d_in[1];
    float* out = (float*)d_out;

    cudaFuncSetAttribute(vq_main_kernel,
                         cudaFuncAttributeMaxDynamicSharedMemorySize, SMEM_BYTES);

    vq_prep_kernel<<<MM, 256>>>(emb);
    vq_main_kernel<<<NBLOCKS, 256, SMEM_BYTES>>>(x, emb, out);
    int write_scalars = (out_size >= NTD + 2) ? 1 : 0;
    vq_finalize_kernel<<<1, 512>>>(out, write_scalars);
}

// round 13
// speedup vs baseline: 1.3004x; 1.3004x over previous
#include <cuda_runtime.h>
#include <cuda_bf16.h>
#include <math.h>
#include <stdint.h>

// Problem constants
#define NT    65536
#define DD    256
#define MM    512
#define NTD   16777216
#define MT    128                 // rows per CTA
#define NB    (NT / MT)           // 512 CTAs
#define TAU   2e-3f               // guard band >> 2*eps(bf16x3)

// smem byte offsets
#define SM_AH   0                 // A hi: 128 rows x 512B (256 bf16, full K)
#define SM_AL   65536             // A lo
#define SM_BH   131072            // B hi chunk: 128 codes x 128B (64 bf16)
#define SM_BL   147456            // B lo chunk
#define SM_CS   163840            // c_j [512] f32
#define SM_SX   165888            // sx [128] f32
#define SM_MN1  166400            // [128] f32
#define SM_IX1  166912            // [128] int
#define SM_MN2  167424            // [128] f32
#define SM_RID  167936            // [128] int
#define SM_FLG  168448            // [128] int flagged rows
#define SM_CNT  168960            // int
#define SM_LRED 168976            // [8] f32
#define SMEM_TOTAL 169024

// Device scratch
__device__ float         g_embn[MM * DD];   // normalized codebook [j][k] fp32
__device__ __nv_bfloat16 g_ebH[MM * DD];    // hi split [j][k]
__device__ __nv_bfloat16 g_ebL[MM * DD];    // lo split [j][k]
__device__ float         g_c[MM];
__device__ float         g_loss_part[NB];
__device__ int           g_hist[MM];

__device__ __forceinline__ uint32_t smem_u32(const void* p) {
    uint32_t a;
    asm("{ .reg .u64 t; cvta.to.shared.u64 t, %1; cvt.u32.u64 %0, t; }" : "=r"(a) : "l"(p));
    return a;
}
__device__ __forceinline__ void ldsm4(uint32_t* r, uint32_t addr) {
    asm volatile("ldmatrix.sync.aligned.m8n8.x4.shared.b16 {%0,%1,%2,%3}, [%4];"
        : "=r"(r[0]), "=r"(r[1]), "=r"(r[2]), "=r"(r[3]) : "r"(addr));
}
__device__ __forceinline__ void mma_bf16(float* d, uint32_t a0, uint32_t a1,
                                         uint32_t a2, uint32_t a3,
                                         uint32_t b0, uint32_t b1) {
    asm volatile("mma.sync.aligned.m16n8k16.row.col.f32.bf16.bf16.f32 "
        "{%0,%1,%2,%3}, {%4,%5,%6,%7}, {%8,%9}, {%0,%1,%2,%3};"
        : "+f"(d[0]), "+f"(d[1]), "+f"(d[2]), "+f"(d[3])
        : "r"(a0), "r"(a1), "r"(a2), "r"(a3), "r"(b0), "r"(b1));
}

// ---------------------------------------------------------------------------
// Prep: normalize codebook, bf16 hi/lo splits, c_j, zero hist
// ---------------------------------------------------------------------------
__global__ void vq_prep_kernel(const float* __restrict__ emb) {
    int j = blockIdx.x;
    int t = threadIdx.x;
    __shared__ float sq[256];
    __shared__ float norm_s;

    float v = emb[j * DD + t];
    sq[t] = __fmul_rn(v, v);
    __syncthreads();
    if (t < 32) {
        float s = 0.0f;
#pragma unroll
        for (int c = 0; c < 4; c++) s = __fadd_rn(s, sq[4 * t + c]);
#pragma unroll
        for (int c = 0; c < 4; c++) s = __fadd_rn(s, sq[128 + 4 * t + c]);
#pragma unroll
        for (int off = 16; off > 0; off >>= 1)
            s = __fadd_rn(s, __shfl_xor_sync(0xffffffffu, s, off));
        if (t == 0) norm_s = sqrtf(s);
    }
    __syncthreads();

    float e = v / __fadd_rn(norm_s, 1e-4f);
    g_embn[j * DD + t] = e;
    __nv_bfloat16 hi = __float2bfloat16(e);
    __nv_bfloat16 lo = __float2bfloat16(__fadd_rn(e, -__bfloat162float(hi)));
    g_ebH[j * DD + t] = hi;
    g_ebL[j * DD + t] = lo;

    sq[t] = __fmul_rn(e, e);
    __syncthreads();
    if (t < 32) {
        float s = 0.0f;
#pragma unroll
        for (int c = 0; c < 4; c++) s = __fadd_rn(s, sq[4 * t + c]);
#pragma unroll
        for (int c = 0; c < 4; c++) s = __fadd_rn(s, sq[128 + 4 * t + c]);
#pragma unroll
        for (int off = 16; off > 0; off >>= 1)
            s = __fadd_rn(s, __shfl_xor_sync(0xffffffffu, s, off));
        if (t == 0) { g_c[j] = s; g_hist[j] = 0; }
    }
}

// ---------------------------------------------------------------------------
// Main: 128 rows x 512 codes per CTA via mma.sync bf16x3 + guarded rescore
// ---------------------------------------------------------------------------
__global__ void __launch_bounds__(256, 1)
vq_main_kernel(const float* __restrict__ x,
               const float* __restrict__ emb,
               float* __restrict__ out) {
    extern __shared__ char smem[];
    const uint32_t sb = smem_u32(smem);
    const int tid = threadIdx.x;
    const int wid = tid >> 5;
    const int lid = tid & 31;
    const long r0 = (long)blockIdx.x * MT;

    float* c_s   = (float*)(smem + SM_CS);
    float* sx_s  = (float*)(smem + SM_SX);
    float* mn1_s = (float*)(smem + SM_MN1);
    int*   ix1_s = (int*)(smem + SM_IX1);
    float* mn2_s = (float*)(smem + SM_MN2);
    int*   rid_s = (int*)(smem + SM_RID);
    int*   flg_s = (int*)(smem + SM_FLG);
    int*   cnt_s = (int*)(smem + SM_CNT);
    float* lred  = (float*)(smem + SM_LRED);

    const float4* xg4 = (const float4*)(x + r0 * DD);   // 64 float4 per row

    // c_j
    for (int i = tid; i < MM; i += 256) c_s[i] = g_c[i];
    if (tid == 0) cnt_s[0] = 0;

    // sx per row (bit-identical to R6: rounded squares + xor tree)
    for (int rr = 0; rr < 16; rr++) {
        int row = wid * 16 + rr;
        float4 a  = xg4[row * 64 + lid];
        float4 bq = xg4[row * 64 + 32 + lid];
        float s = 0.0f;
        s = __fadd_rn(s, __fmul_rn(a.x, a.x));
        s = __fadd_rn(s, __fmul_rn(a.y, a.y));
        s = __fadd_rn(s, __fmul_rn(a.z, a.z));
        s = __fadd_rn(s, __fmul_rn(a.w, a.w));
        s = __fadd_rn(s, __fmul_rn(bq.x, bq.x));
        s = __fadd_rn(s, __fmul_rn(bq.y, bq.y));
        s = __fadd_rn(s, __fmul_rn(bq.z, bq.z));
        s = __fadd_rn(s, __fmul_rn(bq.w, bq.w));
#pragma unroll
        for (int off = 16; off > 0; off >>= 1)
            s = __fadd_rn(s, __shfl_xor_sync(0xffffffffu, s, off));
        if (lid == 0) sx_s[row] = s;
    }

    // A fill (once): x -> bf16 hi/lo, swizzled [row][256 bf16] pitch 512B
#pragma unroll
    for (int i = 0; i < 32; i++) {
        int v   = tid + i * 256;      // 8192 float4
        int row = v >> 6;
        int kq  = v & 63;
        float4 f = xg4[row * 64 + kq];
        __nv_bfloat16 h0 = __float2bfloat16(f.x), h1 = __float2bfloat16(f.y);
        __nv_bfloat16 h2 = __float2bfloat16(f.z), h3 = __float2bfloat16(f.w);
        __nv_bfloat16 l0 = __float2bfloat16(__fadd_rn(f.x, -__bfloat162float(h0)));
        __nv_bfloat16 l1 = __float2bfloat16(__fadd_rn(f.y, -__bfloat162float(h1)));
        __nv_bfloat16 l2 = __float2bfloat16(__fadd_rn(f.z, -__bfloat162float(h2)));
        __nv_bfloat16 l3 = __float2bfloat16(__fadd_rn(f.w, -__bfloat162float(h3)));
        uint32_t ofs = (uint32_t)(kq * 8) ^ ((uint32_t)(row & 7) * 16);
        uint32_t base = row * 512 + ofs;
        __nv_bfloat162* ph = (__nv_bfloat162*)(smem + SM_AH + base);
        ph[0] = __nv_bfloat162(h0, h1); ph[1] = __nv_bfloat162(h2, h3);
        __nv_bfloat162* pl = (__nv_bfloat162*)(smem + SM_AL + base);
        pl[0] = __nv_bfloat162(l0, l1); pl[1] = __nv_bfloat162(l2, l3);
    }

    // lane-invariant ldmatrix address pieces
    const int arow = wid * 16 + (lid & 7) + (lid & 8);
    const uint32_t a_rowoff = (uint32_t)arow * 512;
    const uint32_t a_rowxor = (uint32_t)(arow & 7) * 16;
    const uint32_t a_coladd = (uint32_t)(lid & 16);      // +16B for k+8 matrices
    const int      b_lrow   = (lid & 7) + ((lid & 16) >> 1);
    const uint32_t b_coladd = (uint32_t)(lid & 8) * 2;   // +16B for k+8 matrices

    // per-thread row slots
    const int r_lo = wid * 16 + (lid >> 2);
    const int r_hi = r_lo + 8;

    float mn1[2] = {INFINITY, INFINITY};
    float mn2[2] = {INFINITY, INFINITY};
    int   ix1[2] = {0, 0};

    for (int ct = 0; ct < 4; ct++) {
        float acc[16][4];
#pragma unroll
        for (int n = 0; n < 16; n++)
#pragma unroll
            for (int c = 0; c < 4; c++) acc[n][c] = 0.0f;

        for (int kc = 0; kc < 4; kc++) {
            __syncthreads();   // B buffer reusable
            // fill B hi/lo chunk: 128 codes x 64 bf16, swizzled pitch 128B
#pragma unroll
            for (int i = 0; i < 8; i++) {
                int v = tid + i * 256;          // 2048 uint4 total
                int buf = v >> 10;              // 0 = hi, 1 = lo
                int j   = (v & 1023) >> 3;
                int q   = v & 7;
                const char* src = buf ? (const char*)g_ebL : (const char*)g_ebH;
                uint4 u = *(const uint4*)(src +
                    ((long)(ct * 128 + j) * DD + kc * 64 + q * 8) * 2);
                uint32_t ofs = ((uint32_t)(q * 16)) ^ ((uint32_t)(j & 7) * 16);
                *(uint4*)(smem + (buf ? SM_BL : SM_BH) + j * 128 + ofs) = u;
            }
            __syncthreads();

#pragma unroll
            for (int ks = 0; ks < 4; ks++) {
                uint32_t cbA = (uint32_t)(kc * 128 + ks * 32) + a_coladd;
                uint32_t ah[4], al[4];
                ldsm4(ah, sb + SM_AH + a_rowoff + (cbA ^ a_rowxor));
                ldsm4(al, sb + SM_AL + a_rowoff + (cbA ^ a_rowxor));
                uint32_t cbB = (uint32_t)(ks * 32) + b_coladd;
#pragma unroll
                for (int nt2 = 0; nt2 < 8; nt2++) {
                    int code = nt2 * 16 + b_lrow;
                    uint32_t boff = (uint32_t)code * 128 +
                                    (cbB ^ ((uint32_t)(code & 7) * 16));
                    uint32_t bh[4], bl[4];
                    ldsm4(bh, sb + SM_BH + boff);
                    ldsm4(bl, sb + SM_BL + boff);
                    mma_bf16(acc[nt2 * 2],     ah[0], ah[1], ah[2], ah[3], bh[0], bh[1]);
                    mma_bf16(acc[nt2 * 2 + 1], ah[0], ah[1], ah[2], ah[3], bh[2], bh[3]);
                    mma_bf16(acc[nt2 * 2],     al[0], al[1], al[2], al[3], bh[0], bh[1]);
                    mma_bf16(acc[nt2 * 2 + 1], al[0], al[1], al[2], al[3], bh[2], bh[3]);
                    mma_bf16(acc[nt2 * 2],     ah[0], ah[1], ah[2], ah[3], bl[0], bl[1]);
                    mma_bf16(acc[nt2 * 2 + 1], ah[0], ah[1], ah[2], ah[3], bl[2], bl[3]);
                }
            }
        }

        // fold this code tile into running mins (reference-rounded metric)
        float sxlo = sx_s[r_lo], sxhi = sx_s[r_hi];
#pragma unroll
        for (int nt = 0; nt < 16; nt++) {
            int j0 = ct * 128 + nt * 8 + (lid & 3) * 2;
#pragma unroll
            for (int c = 0; c < 4; c++) {
                int slot = (c >> 1);
                int j = j0 + (c & 1);
                float sx = slot ? sxhi : sxlo;
                float m = __fadd_rn(__fadd_rn(c_s[j], sx), -2.0f * acc[nt][c]);
                if (m < mn1[slot]) { mn2[slot] = mn1[slot]; mn1[slot] = m; ix1[slot] = j; }
                else if (m < mn2[slot]) mn2[slot] = m;
            }
        }
    }

    // merge across the 4 lanes that share each row (xor 1, 2)
#pragma unroll
    for (int s = 0; s < 2; s++) {
#pragma unroll
        for (int off = 1; off <= 2; off <<= 1) {
            float om1 = __shfl_xor_sync(0xffffffffu, mn1[s], off);
            int   oi1 = __shfl_xor_sync(0xffffffffu, ix1[s], off);
            float om2 = __shfl_xor_sync(0xffffffffu, mn2[s], off);
            float nm2 = fminf(fminf(mn2[s], om2), fmaxf(mn1[s], om1));
            if (om1 < mn1[s] || (om1 == mn1[s] && oi1 < ix1[s])) {
                mn1[s] = om1; ix1[s] = oi1;
            }
            mn2[s] = nm2;
        }
    }
    if ((lid & 3) == 0) {
        mn1_s[r_lo] = mn1[0]; ix1_s[r_lo] = ix1[0]; mn2_s[r_lo] = mn2[0];
        mn1_s[r_hi] = mn1[1]; ix1_s[r_hi] = ix1[1]; mn2_s[r_hi] = mn2[1];
    }
    __syncthreads();

    // guard: flag rows needing exact rescore
    if (tid < MT) {
        int row = tid;
        rid_s[row] = ix1_s[row];
        if (mn2_s[row] <= __fadd_rn(mn1_s[row], TAU)) {
            int p = atomicAdd(cnt_s, 1);
            flg_s[p] = row;
        }
    }
    __syncthreads();

    // exact rescan of flagged rows (bit-identical R6 chain, lowest-idx ties)
    {
        int nflag = cnt_s[0];
        for (int f = wid; f < nflag; f += 8) {
            int row = flg_s[f];
            const float4* xr4 = (const float4*)(x + (r0 + row) * DD);
            float sx = sx_s[row];
            float bv = INFINITY; int bi = 0;
            for (int t = 0; t < 16; t++) {
                int j = t * 32 + lid;
                const float4* er4 = (const float4*)(g_embn + j * DD);
                float acc = 0.0f;
#pragma unroll 8
                for (int q = 0; q < 64; q++) {
                    float4 a = xr4[q], e = er4[q];
                    acc = fmaf(a.x, e.x, acc);
                    acc = fmaf(a.y, e.y, acc);
                    acc = fmaf(a.z, e.z, acc);
                    acc = fmaf(a.w, e.w, acc);
                }
                float me = __fadd_rn(__fadd_rn(c_s[j], sx), -2.0f * acc);
                if (me < bv) { bv = me; bi = j; }
            }
#pragma unroll
            for (int off = 16; off > 0; off >>= 1) {
                float ov = __shfl_xor_sync(0xffffffffu, bv, off);
                int   oi = __shfl_xor_sync(0xffffffffu, bi, off);
                if (ov < bv || (ov == bv && oi < bi)) { bv = ov; bi = oi; }
            }
            if (lid == 0) rid_s[row] = bi;
        }
    }
    __syncthreads();

    if (tid < MT) atomicAdd(&g_hist[rid_s[tid]], 1);

    // gather + straight-through + loss (bit-identical arithmetic)
    float lsum = 0.0f;
    {
        int r  = tid >> 1;
        int kb = (tid & 1) * 128;
        int idx = rid_s[r];
        const float4* eq = (const float4*)(emb + (long)idx * DD + kb);
        const float4* xq = (const float4*)(x + (r0 + r) * DD + kb);
        float4*       og = (float4*)(out + (r0 + r) * DD + kb);
#pragma unroll
        for (int i = 0; i < 32; i++) {
            float4 q = eq[i];
            float4 xv = xq[i];
            float4 o;
            o.x = __fmul_rn(__fadd_rn(__fadd_rn(xv.x, __fadd_rn(q.x, -xv.x)), q.x), 0.5f);
            o.y = __fmul_rn(__fadd_rn(__fadd_rn(xv.y, __fadd_rn(q.y, -xv.y)), q.y), 0.5f);
            o.z = __fmul_rn(__fadd_rn(__fadd_rn(xv.z, __fadd_rn(q.z, -xv.z)), q.z), 0.5f);
            o.w = __fmul_rn(__fadd_rn(__fadd_rn(xv.w, __fadd_rn(q.w, -xv.w)), q.w), 0.5f);
            og[i] = o;
            float d0 = __fadd_rn(xv.x, -q.x);
            float d1 = __fadd_rn(xv.y, -q.y);
            float d2 = __fadd_rn(xv.z, -q.z);
            float d3 = __fadd_rn(xv.w, -q.w);
            lsum += d0 * d0 + d1 * d1 + d2 * d2 + d3 * d3;
        }
    }
#pragma unroll
    for (int off = 16; off > 0; off >>= 1)
        lsum += __shfl_down_sync(0xffffffffu, lsum, off);
    if (lid == 0) lred[wid] = lsum;
    __syncthreads();
    if (tid == 0) {
        float tot = 0.0f;
        for (int w = 0; w < 8; w++) tot += lred[w];
        g_loss_part[blockIdx.x] = tot;
    }
}

// ---------------------------------------------------------------------------
// Finalize: loss mean + perplexity. 1 block x 512 threads.
// ---------------------------------------------------------------------------
__global__ void vq_finalize_kernel(float* __restrict__ out, int write_scalars) {
    __shared__ float red[512];
    int t = threadIdx.x;

    red[t] = g_loss_part[t];
    __syncthreads();
#pragma unroll
    for (int st = 256; st > 0; st >>= 1) {
        if (t < st) red[t] += red[t + st];
        __syncthreads();
    }
    float loss = red[0] / (float)NTD;

    float p = (float)g_hist[t] * (1.0f / (float)NT);
    red[t] = p * logf(p + 1e-10f);
    __syncthreads();
#pragma unroll
    for (int st = 256; st > 0; st >>= 1) {
        if (t < st) red[t] += red[t + st];
        __syncthreads();
    }
    if (t == 0 && write_scalars) {
        out[NTD]     = loss;
        out[NTD + 1] = expf(-red[0]);
    }
}

// ---------------------------------------------------------------------------
extern "C" void kernel_launch(void* const* d_in, const int* in_sizes, int n_in,
                              void* d_out, int out_size) {
    const float* x   = (const float*)d_in[0];
    const float* emb = (const float*)d_in[1];
    float* out = (float*)d_out;

    cudaFuncSetAttribute(vq_main_kernel,
                         cudaFuncAttributeMaxDynamicSharedMemorySize, SMEM_TOTAL);

    vq_prep_kernel<<<MM, 256>>>(emb);
    vq_main_kernel<<<NB, 256, SMEM_TOTAL>>>(x, emb, out);
    int write_scalars = (out_size >= NTD + 2) ? 1 : 0;
    vq_finalize_kernel<<<1, 512>>>(out, write_scalars);
}

// round 14
// speedup vs baseline: 1.8855x; 1.4499x over previous
#include <cuda_runtime.h>
#include <cuda_bf16.h>
#include <math.h>
#include <stdint.h>

// Problem constants
#define NT    65536
#define DD    256
#define MM    512
#define NTD   16777216
#define MT    128                 // rows per CTA
#define NB    (NT / MT)           // 512 CTAs
#define TAU   0.03f               // guard band ~8 sigma of bf16 hi-only error

// smem byte offsets
#define SM_A     0                // A hi: 128 rows x 512B (256 bf16, full K)
#define SM_B0    65536            // B chunk buf0: 128 codes x 128B (64 bf16)
#define SM_B1    81920            // B chunk buf1
#define SM_CS    98304            // c_j [512] f32
#define SM_SX    100352           // sx [128] f32
#define SM_M1    100864           // [128] f32
#define SM_I1    101376           // [128] int
#define SM_M2    101888           // [128] f32
#define SM_I2    102400           // [128] int
#define SM_M3    102912           // [128] f32
#define SM_RID   103424           // [128] int
#define SM_FLGA  103936           // [128] rows needing full rescan
#define SM_FLGB  104448           // [128] rows needing pair rescore
#define SM_IXB1  104960           // [128] pair candidate 1
#define SM_IXB2  105472           // [128] pair candidate 2
#define SM_CNT   105984           // [2] int: cntA, cntB
#define SM_LRED  105992           // [8] f32
#define SMEM_TOTAL 106048

// Device scratch
__device__ float         g_embn[MM * DD];   // normalized codebook [j][k] fp32
__device__ __nv_bfloat16 g_ebH[MM * DD];    // bf16 hi [j][k]
__device__ float         g_c[MM];
__device__ float         g_loss_part[NB];
__device__ int           g_hist[MM];

__device__ __forceinline__ uint32_t smem_u32(const void* p) {
    uint32_t a;
    asm("{ .reg .u64 t; cvta.to.shared.u64 t, %1; cvt.u32.u64 %0, t; }" : "=r"(a) : "l"(p));
    return a;
}
__device__ __forceinline__ void ldsm4(uint32_t* r, uint32_t addr) {
    asm volatile("ldmatrix.sync.aligned.m8n8.x4.shared.b16 {%0,%1,%2,%3}, [%4];"
        : "=r"(r[0]), "=r"(r[1]), "=r"(r[2]), "=r"(r[3]) : "r"(addr));
}
__device__ __forceinline__ void mma_bf16(float* d, const uint32_t* a,
                                         uint32_t b0, uint32_t b1) {
    asm volatile("mma.sync.aligned.m16n8k16.row.col.f32.bf16.bf16.f32 "
        "{%0,%1,%2,%3}, {%4,%5,%6,%7}, {%8,%9}, {%0,%1,%2,%3};"
        : "+f"(d[0]), "+f"(d[1]), "+f"(d[2]), "+f"(d[3])
        : "r"(a[0]), "r"(a[1]), "r"(a[2]), "r"(a[3]), "r"(b0), "r"(b1));
}
#define CP_ASYNC16(saddr, gptr) \
    asm volatile("cp.async.cg.shared.global [%0], [%1], 16;" :: "r"(saddr), "l"(gptr))
#define CP_COMMIT() asm volatile("cp.async.commit_group;" ::: "memory")
#define CP_WAIT0()  asm volatile("cp.async.wait_group 0;" ::: "memory")

// top-3 tracker (indices for top-2 only; m3 is a value bound)
struct Top3 { float m1, m2, m3; int i1, i2; };
__device__ __forceinline__ void t3_ins(Top3& t, float m, int i) {
    if (m < t.m1 || (m == t.m1 && i < t.i1)) {
        t.m3 = t.m2; t.m2 = t.m1; t.i2 = t.i1; t.m1 = m; t.i1 = i;
    } else if (m < t.m2 || (m == t.m2 && i < t.i2)) {
        t.m3 = t.m2; t.m2 = m; t.i2 = i;
    } else if (m < t.m3) t.m3 = m;
}

// ---------------------------------------------------------------------------
// Prep: normalize codebook, bf16 hi split, c_j, zero hist
// ---------------------------------------------------------------------------
__global__ void vq_prep_kernel(const float* __restrict__ emb) {
    int j = blockIdx.x;
    int t = threadIdx.x;
    __shared__ float sq[256];
    __shared__ float norm_s;

    float v = emb[j * DD + t];
    sq[t] = __fmul_rn(v, v);
    __syncthreads();
    if (t < 32) {
        float s = 0.0f;
#pragma unroll
        for (int c = 0; c < 4; c++) s = __fadd_rn(s, sq[4 * t + c]);
#pragma unroll
        for (int c = 0; c < 4; c++) s = __fadd_rn(s, sq[128 + 4 * t + c]);
#pragma unroll
        for (int off = 16; off > 0; off >>= 1)
            s = __fadd_rn(s, __shfl_xor_sync(0xffffffffu, s, off));
        if (t == 0) norm_s = sqrtf(s);
    }
    __syncthreads();

    float e = v / __fadd_rn(norm_s, 1e-4f);
    g_embn[j * DD + t] = e;
    g_ebH[j * DD + t] = __float2bfloat16(e);

    sq[t] = __fmul_rn(e, e);
    __syncthreads();
    if (t < 32) {
        float s = 0.0f;
#pragma unroll
        for (int c = 0; c < 4; c++) s = __fadd_rn(s, sq[4 * t + c]);
#pragma unroll
        for (int c = 0; c < 4; c++) s = __fadd_rn(s, sq[128 + 4 * t + c]);
#pragma unroll
        for (int off = 16; off > 0; off >>= 1)
            s = __fadd_rn(s, __shfl_xor_sync(0xffffffffu, s, off));
        if (t == 0) { g_c[j] = s; g_hist[j] = 0; }
    }
}

// exact dot chain, bit-identical to R6 (sequential ascending-k fmaf)
__device__ __forceinline__ float exact_metric(const float4* xr4, int code,
                                              float c, float sx) {
    const float4* er4 = (const float4*)(g_embn + code * DD);
    float acc = 0.0f;
#pragma unroll 8
    for (int q = 0; q < 64; q++) {
        float4 a = xr4[q], e = er4[q];
        acc = fmaf(a.x, e.x, acc);
        acc = fmaf(a.y, e.y, acc);
        acc = fmaf(a.z, e.z, acc);
        acc = fmaf(a.w, e.w, acc);
    }
    return __fadd_rn(__fadd_rn(c, sx), -2.0f * acc);
}

// ---------------------------------------------------------------------------
// Main: 128 rows x 512 codes per CTA, single-pass bf16 mma + guarded rescore
// ---------------------------------------------------------------------------
__global__ void __launch_bounds__(256, 2)
vq_main_kernel(const float* __restrict__ x,
               const float* __restrict__ emb,
               float* __restrict__ out) {
    extern __shared__ char smem[];
    const uint32_t sb = smem_u32(smem);
    const int tid = threadIdx.x;
    const int wid = tid >> 5;
    const int lid = tid & 31;
    const long r0 = (long)blockIdx.x * MT;

    float* c_s   = (float*)(smem + SM_CS);
    float* sx_s  = (float*)(smem + SM_SX);
    float* m1_s  = (float*)(smem + SM_M1);
    int*   i1_s  = (int*)(smem + SM_I1);
    float* m2_s  = (float*)(smem + SM_M2);
    int*   i2_s  = (int*)(smem + SM_I2);
    float* m3_s  = (float*)(smem + SM_M3);
    int*   rid_s = (int*)(smem + SM_RID);
    int*   flgA  = (int*)(smem + SM_FLGA);
    int*   flgB  = (int*)(smem + SM_FLGB);
    int*   ixb1  = (int*)(smem + SM_IXB1);
    int*   ixb2  = (int*)(smem + SM_IXB2);
    int*   cnt_s = (int*)(smem + SM_CNT);
    float* lred  = (float*)(smem + SM_LRED);

    const float4* xg4 = (const float4*)(x + r0 * DD);   // 64 float4 per row

    // c_j
    for (int i = tid; i < MM; i += 256) c_s[i] = g_c[i];
    if (tid < 2) cnt_s[tid] = 0;

    // sx per row (bit-identical to R6)
    for (int rr = 0; rr < 16; rr++) {
        int row = wid * 16 + rr;
        float4 a  = xg4[row * 64 + lid];
        float4 bq = xg4[row * 64 + 32 + lid];
        float s = 0.0f;
        s = __fadd_rn(s, __fmul_rn(a.x, a.x));
        s = __fadd_rn(s, __fmul_rn(a.y, a.y));
        s = __fadd_rn(s, __fmul_rn(a.z, a.z));
        s = __fadd_rn(s, __fmul_rn(a.w, a.w));
        s = __fadd_rn(s, __fmul_rn(bq.x, bq.x));
        s = __fadd_rn(s, __fmul_rn(bq.y, bq.y));
        s = __fadd_rn(s, __fmul_rn(bq.z, bq.z));
        s = __fadd_rn(s, __fmul_rn(bq.w, bq.w));
#pragma unroll
        for (int off = 16; off > 0; off >>= 1)
            s = __fadd_rn(s, __shfl_xor_sync(0xffffffffu, s, off));
        if (lid == 0) sx_s[row] = s;
    }

    // A fill (once): x -> bf16 hi, swizzled [row][256 bf16] pitch 512B
#pragma unroll
    for (int i = 0; i < 32; i++) {
        int v   = tid + i * 256;      // 8192 float4
        int row = v >> 6;
        int kq  = v & 63;
        float4 f = xg4[row * 64 + kq];
        __nv_bfloat16 h0 = __float2bfloat16(f.x), h1 = __float2bfloat16(f.y);
        __nv_bfloat16 h2 = __float2bfloat16(f.z), h3 = __float2bfloat16(f.w);
        uint32_t ofs = (uint32_t)(kq * 8) ^ ((uint32_t)(row & 7) * 16);
        __nv_bfloat162* ph = (__nv_bfloat162*)(smem + SM_A + row * 512 + ofs);
        ph[0] = __nv_bfloat162(h0, h1);
        ph[1] = __nv_bfloat162(h2, h3);
    }

    // prefetch chunk 0 (ct=0, kc=0) into buf0 via cp.async
    {
#pragma unroll
        for (int i = 0; i < 4; i++) {
            int v = tid + i * 256;          // 1024 uint4
            int j = v >> 3, q = v & 7;
            const char* src = (const char*)g_ebH + ((long)j * DD + q * 8) * 2;
            uint32_t dst = sb + SM_B0 + j * 128 +
                           (((uint32_t)(q * 16)) ^ ((uint32_t)(j & 7) * 16));
            CP_ASYNC16(dst, src);
        }
        CP_COMMIT();
    }

    // lane-invariant ldmatrix address pieces (verified in R13)
    const int arow = wid * 16 + (lid & 7) + (lid & 8);
    const uint32_t a_rowoff = (uint32_t)arow * 512;
    const uint32_t a_rowxor = (uint32_t)(arow & 7) * 16;
    const uint32_t a_coladd = (uint32_t)(lid & 16);
    const int      b_lrow   = (lid & 7) + ((lid & 16) >> 1);
    const uint32_t b_coladd = (uint32_t)(lid & 8) * 2;

    const int r_lo = wid * 16 + (lid >> 2);
    const int r_hi = r_lo + 8;

    Top3 t3[2];
#pragma unroll
    for (int s = 0; s < 2; s++) {
        t3[s].m1 = t3[s].m2 = t3[s].m3 = INFINITY;
        t3[s].i1 = t3[s].i2 = 0;
    }

    int cc = 0;
    for (int ct = 0; ct < 4; ct++) {
        float acc[16][4];
#pragma unroll
        for (int n = 0; n < 16; n++)
#pragma unroll
            for (int c = 0; c < 4; c++) acc[n][c] = 0.0f;

        for (int kc = 0; kc < 4; kc++) {
            CP_WAIT0();
            __syncthreads();                    // chunk cc visible to all

            if (cc < 15) {                      // prefetch next chunk
                int nct = (cc + 1) >> 2, nkc = (cc + 1) & 3;
                uint32_t nb = sb + (((cc + 1) & 1) ? SM_B1 : SM_B0);
#pragma unroll
                for (int i = 0; i < 4; i++) {
                    int v = tid + i * 256;
                    int j = v >> 3, q = v & 7;
                    const char* src = (const char*)g_ebH +
                        ((long)(nct * 128 + j) * DD + nkc * 64 + q * 8) * 2;
                    uint32_t dst = nb + j * 128 +
                        (((uint32_t)(q * 16)) ^ ((uint32_t)(j & 7) * 16));
                    CP_ASYNC16(dst, src);
                }
                CP_COMMIT();
            }

            const uint32_t bbase = sb + ((cc & 1) ? SM_B1 : SM_B0);
#pragma unroll
            for (int ks = 0; ks < 4; ks++) {
                uint32_t cbA = (uint32_t)(kc * 128 + ks * 32) + a_coladd;
                uint32_t ah[4];
                ldsm4(ah, sb + SM_A + a_rowoff + (cbA ^ a_rowxor));
                uint32_t cbB = (uint32_t)(ks * 32) + b_coladd;
#pragma unroll
                for (int nt2 = 0; nt2 < 8; nt2++) {
                    int code = nt2 * 16 + b_lrow;
                    uint32_t boff = (uint32_t)code * 128 +
                                    (cbB ^ ((uint32_t)(code & 7) * 16));
                    uint32_t bh[4];
                    ldsm4(bh, bbase + boff);
                    mma_bf16(acc[nt2 * 2],     ah, bh[0], bh[1]);
                    mma_bf16(acc[nt2 * 2 + 1], ah, bh[2], bh[3]);
                }
            }
            __syncthreads();                    // protect buffer for next prefetch
            cc++;
        }

        // fold this code tile (reference-rounded metric) into top-3
        float sxv[2] = {sx_s[r_lo], sx_s[r_hi]};
#pragma unroll
        for (int nt = 0; nt < 16; nt++) {
            int j0 = ct * 128 + nt * 8 + (lid & 3) * 2;
#pragma unroll
            for (int c = 0; c < 4; c++) {
                int slot = c >> 1;
                int j = j0 + (c & 1);
                float m = __fadd_rn(__fadd_rn(c_s[j], sxv[slot]), -2.0f * acc[nt][c]);
                t3_ins(t3[slot], m, j);
            }
        }
    }

    // merge across the 4 lanes sharing each row (xor 1, 2)
#pragma unroll
    for (int s = 0; s < 2; s++) {
#pragma unroll
        for (int off = 1; off <= 2; off <<= 1) {
            float om1 = __shfl_xor_sync(0xffffffffu, t3[s].m1, off);
            int   oi1 = __shfl_xor_sync(0xffffffffu, t3[s].i1, off);
            float om2 = __shfl_xor_sync(0xffffffffu, t3[s].m2, off);
            int   oi2 = __shfl_xor_sync(0xffffffffu, t3[s].i2, off);
            float om3 = __shfl_xor_sync(0xffffffffu, t3[s].m3, off);
            t3_ins(t3[s], om1, oi1);
            t3_ins(t3[s], om2, oi2);
            if (om3 < t3[s].m3) t3[s].m3 = om3;   // om3 >= merged m2, value-only ok
        }
    }
    if ((lid & 3) == 0) {
        m1_s[r_lo] = t3[0].m1; i1_s[r_lo] = t3[0].i1;
        m2_s[r_lo] = t3[0].m2; i2_s[r_lo] = t3[0].i2; m3_s[r_lo] = t3[0].m3;
        m1_s[r_hi] = t3[1].m1; i1_s[r_hi] = t3[1].i1;
        m2_s[r_hi] = t3[1].m2; i2_s[r_hi] = t3[1].i2; m3_s[r_hi] = t3[1].m3;
    }
    __syncthreads();

    // classify rows
    if (tid < MT) {
        int row = tid;
        rid_s[row] = i1_s[row];
        float lim = m1_s[row] + TAU;
        if (m3_s[row] <= lim) {                 // rare: full exact rescan
            int p = atomicAdd(&cnt_s[0], 1);
            flgA[p] = row;
        } else if (m2_s[row] <= lim) {          // pair rescore
            int p = atomicAdd(&cnt_s[1], 1);
            flgB[p] = row; ixb1[p] = i1_s[row]; ixb2[p] = i2_s[row];
        }
    }
    __syncthreads();

    // pair rescores: warp 0, 16 pairs at a time (lane pairs)
    if (wid == 0) {
        int cntB = cnt_s[1];
        for (int base = 0; base < cntB; base += 16) {
            int e = base + (lid >> 1);
            bool act = e < cntB;
            int row = 0, code = 0;
            float me = INFINITY;
            if (act) {
                row  = flgB[e];
                code = (lid & 1) ? ixb2[e] : ixb1[e];
                me = exact_metric((const float4*)(x + (r0 + row) * DD),
                                  code, c_s[code], sx_s[row]);
            }
            float om = __shfl_xor_sync(0xffffffffu, me, 1);
            int   oc = __shfl_xor_sync(0xffffffffu, code, 1);
            if (act && !(lid & 1)) {
                rid_s[row] = (me < om || (me == om && code < oc)) ? code : oc;
            }
        }
    }
    // full rescans: warps 1..7
    if (wid >= 1) {
        int cntA = cnt_s[0];
        for (int f = wid - 1; f < cntA; f += 7) {
            int row = flgA[f];
            const float4* xr4 = (const float4*)(x + (r0 + row) * DD);
            float sx = sx_s[row];
            float bv = INFINITY; int bi = 0;
            for (int t = 0; t < 16; t++) {
                int j = t * 32 + lid;
                float me = exact_metric(xr4, j, c_s[j], sx);
                if (me < bv) { bv = me; bi = j; }
            }
#pragma unroll
            for (int off = 16; off > 0; off >>= 1) {
                float ov = __shfl_xor_sync(0xffffffffu, bv, off);
                int   oi = __shfl_xor_sync(0xffffffffu, bi, off);
                if (ov < bv || (ov == bv && oi < bi)) { bv = ov; bi = oi; }
            }
            if (lid == 0) rid_s[row] = bi;
        }
    }
    __syncthreads();

    if (tid < MT) atomicAdd(&g_hist[rid_s[tid]], 1);

    // gather + straight-through + loss (bit-identical arithmetic)
    float lsum = 0.0f;
    {
        int r  = tid >> 1;
        int kb = (tid & 1) * 128;
        int idx = rid_s[r];
        const float4* eq = (const float4*)(emb + (long)idx * DD + kb);
        const float4* xq = (const float4*)(x + (r0 + r) * DD + kb);
        float4*       og = (float4*)(out + (r0 + r) * DD + kb);
#pragma unroll
        for (int i = 0; i < 32; i++) {
            float4 q = eq[i];
            float4 xv = xq[i];
            float4 o;
            o.x = __fmul_rn(__fadd_rn(__fadd_rn(xv.x, __fadd_rn(q.x, -xv.x)), q.x), 0.5f);
            o.y = __fmul_rn(__fadd_rn(__fadd_rn(xv.y, __fadd_rn(q.y, -xv.y)), q.y), 0.5f);
            o.z = __fmul_rn(__fadd_rn(__fadd_rn(xv.z, __fadd_rn(q.z, -xv.z)), q.z), 0.5f);
            o.w = __fmul_rn(__fadd_rn(__fadd_rn(xv.w, __fadd_rn(q.w, -xv.w)), q.w), 0.5f);
            og[i] = o;
            float d0 = __fadd_rn(xv.x, -q.x);
            float d1 = __fadd_rn(xv.y, -q.y);
            float d2 = __fadd_rn(xv.z, -q.z);
            float d3 = __fadd_rn(xv.w, -q.w);
            lsum += d0 * d0 + d1 * d1 + d2 * d2 + d3 * d3;
        }
    }
#pragma unroll
    for (int off = 16; off > 0; off >>= 1)
        lsum += __shfl_down_sync(0xffffffffu, lsum, off);
    if (lid == 0) lred[wid] = lsum;
    __syncthreads();
    if (tid == 0) {
        float tot = 0.0f;
        for (int w = 0; w < 8; w++) tot += lred[w];
        g_loss_part[blockIdx.x] = tot;
    }
}

// ---------------------------------------------------------------------------
// Finalize: loss mean + perplexity. 1 block x 512 threads.
// ---------------------------------------------------------------------------
__global__ void vq_finalize_kernel(float* __restrict__ out, int write_scalars) {
    __shared__ float red[512];
    int t = threadIdx.x;

    red[t] = g_loss_part[t];
    __syncthreads();
#pragma unroll
    for (int st = 256; st > 0; st >>= 1) {
        if (t < st) red[t] += red[t + st];
        __syncthreads();
    }
    float loss = red[0] / (float)NTD;

    float p = (float)g_hist[t] * (1.0f / (float)NT);
    red[t] = p * logf(p + 1e-10f);
    __syncthreads();
#pragma unroll
    for (int st = 256; st > 0; st >>= 1) {
        if (t < st) red[t] += red[t + st];
        __syncthreads();
    }
    if (t == 0 && write_scalars) {
        out[NTD]     = loss;
        out[NTD + 1] = expf(-red[0]);
    }
}

// ---------------------------------------------------------------------------
extern "C" void kernel_launch(void* const* d_in, const int* in_sizes, int n_in,
                              void* d_out, int out_size) {
    const float* x   = (const float*)d_in[0];
    const float* emb = (const float*)d_in[1];
    float* out = (float*)d_out;

    cudaFuncSetAttribute(vq_main_kernel,
                         cudaFuncAttributeMaxDynamicSharedMemorySize, SMEM_TOTAL);

    vq_prep_kernel<<<MM, 256>>>(emb);
    vq_main_kernel<<<NB, 256, SMEM_TOTAL>>>(x, emb, out);
    int write_scalars = (out_size >= NTD + 2) ? 1 : 0;
    vq_finalize_kernel<<<1, 512>>>(out, write_scalars);
}

// round 15
// speedup vs baseline: 1.9299x; 1.0236x over previous
#include <cuda_runtime.h>
#include <cuda_bf16.h>
#include <math.h>
#include <stdint.h>

// Problem constants
#define NT    65536
#define DD    256
#define MM    512
#define NTD   16777216
#define MT    128                 // rows per CTA
#define NB    (NT / MT)           // 512 CTAs
#define TAU   0.03f               // guard band ~8 sigma of bf16 hi-only error

// smem byte offsets
#define SM_A     0                // A hi: 128 rows x 512B (256 bf16, full K)
#define SM_B0    65536            // B chunk buf0: 128 codes x 128B (64 bf16)
#define SM_B1    81920            // B chunk buf1
#define SM_CS    98304            // c_j [512] f32
#define SM_SX    100352           // sx [128] f32 (exact, flagged rows only)
#define SM_M1    100864           // [128] f32
#define SM_I1    101376           // [128] int
#define SM_M2    101888           // [128] f32
#define SM_I2    102400           // [128] int
#define SM_M3    102912           // [128] f32
#define SM_RID   103424           // [128] int
#define SM_FLGA  103936           // [128] rows needing full rescan
#define SM_FLGB  104448           // [128] rows needing pair rescore
#define SM_IXB1  104960           // [128] pair candidate 1
#define SM_IXB2  105472           // [128] pair candidate 2
#define SM_CNT   105984           // [2] int: cntA, cntB
#define SM_LRED  105992           // [8] f32
#define SMEM_TOTAL 106048

// Device scratch
__device__ float         g_embn[MM * DD];   // normalized codebook [j][k] fp32
__device__ __nv_bfloat16 g_ebH[MM * DD];    // bf16 hi [j][k]
__device__ float         g_c[MM];
__device__ float         g_loss_part[NB];
__device__ int           g_hist[MM];

__device__ __forceinline__ uint32_t smem_u32(const void* p) {
    uint32_t a;
    asm("{ .reg .u64 t; cvta.to.shared.u64 t, %1; cvt.u32.u64 %0, t; }" : "=r"(a) : "l"(p));
    return a;
}
__device__ __forceinline__ void ldsm4(uint32_t* r, uint32_t addr) {
    asm volatile("ldmatrix.sync.aligned.m8n8.x4.shared.b16 {%0,%1,%2,%3}, [%4];"
        : "=r"(r[0]), "=r"(r[1]), "=r"(r[2]), "=r"(r[3]) : "r"(addr));
}
__device__ __forceinline__ void mma_bf16(float* d, const uint32_t* a,
                                         uint32_t b0, uint32_t b1) {
    asm volatile("mma.sync.aligned.m16n8k16.row.col.f32.bf16.bf16.f32 "
        "{%0,%1,%2,%3}, {%4,%5,%6,%7}, {%8,%9}, {%0,%1,%2,%3};"
        : "+f"(d[0]), "+f"(d[1]), "+f"(d[2]), "+f"(d[3])
        : "r"(a[0]), "r"(a[1]), "r"(a[2]), "r"(a[3]), "r"(b0), "r"(b1));
}
#define CP_ASYNC16(saddr, gptr) \
    asm volatile("cp.async.cg.shared.global [%0], [%1], 16;" :: "r"(saddr), "l"(gptr))
#define CP_COMMIT() asm volatile("cp.async.commit_group;" ::: "memory")
#define CP_WAIT0()  asm volatile("cp.async.wait_group 0;" ::: "memory")

// packed f32x2 (per-lane IEEE RN; proven to compile for compute_103)
#define ADD2(d, a, b) asm("add.rn.f32x2 %0, %1, %2;" : "=l"(d) : "l"(a), "l"(b))
#define MUL2(d, a, b) asm("mul.rn.f32x2 %0, %1, %2;" : "=l"(d) : "l"(a), "l"(b))
#define FMA2(d, a, b) asm("fma.rn.f32x2 %0, %1, %2, %0;" : "+l"(d) : "l"(a), "l"(b))
#define UNPK2(lo, hi, v) asm("mov.b64 {%0,%1}, %2;" : "=f"(lo), "=f"(hi) : "l"(v))
#define SGN2 0x8000000080000000ull
#define HALF2C 0x3F0000003F000000ull

union F4U { float4 f; unsigned long long u[2]; };

// top-3 tracker (indices for top-2 only; m3 is a value bound)
struct Top3 { float m1, m2, m3; int i1, i2; };
__device__ __forceinline__ void t3_ins(Top3& t, float m, int i) {
    if (m < t.m1 || (m == t.m1 && i < t.i1)) {
        t.m3 = t.m2; t.m2 = t.m1; t.i2 = t.i1; t.m1 = m; t.i1 = i;
    } else if (m < t.m2 || (m == t.m2 && i < t.i2)) {
        t.m3 = t.m2; t.m2 = m; t.i2 = i;
    } else if (m < t.m3) t.m3 = m;
}

// ---------------------------------------------------------------------------
// Prep: normalize codebook, bf16 hi split, c_j, zero hist
// ---------------------------------------------------------------------------
__global__ void vq_prep_kernel(const float* __restrict__ emb) {
    int j = blockIdx.x;
    int t = threadIdx.x;
    __shared__ float sq[256];
    __shared__ float norm_s;

    float v = emb[j * DD + t];
    sq[t] = __fmul_rn(v, v);
    __syncthreads();
    if (t < 32) {
        float s = 0.0f;
#pragma unroll
        for (int c = 0; c < 4; c++) s = __fadd_rn(s, sq[4 * t + c]);
#pragma unroll
        for (int c = 0; c < 4; c++) s = __fadd_rn(s, sq[128 + 4 * t + c]);
#pragma unroll
        for (int off = 16; off > 0; off >>= 1)
            s = __fadd_rn(s, __shfl_xor_sync(0xffffffffu, s, off));
        if (t == 0) norm_s = sqrtf(s);
    }
    __syncthreads();

    float e = v / __fadd_rn(norm_s, 1e-4f);
    g_embn[j * DD + t] = e;
    g_ebH[j * DD + t] = __float2bfloat16(e);

    sq[t] = __fmul_rn(e, e);
    __syncthreads();
    if (t < 32) {
        float s = 0.0f;
#pragma unroll
        for (int c = 0; c < 4; c++) s = __fadd_rn(s, sq[4 * t + c]);
#pragma unroll
        for (int c = 0; c < 4; c++) s = __fadd_rn(s, sq[128 + 4 * t + c]);
#pragma unroll
        for (int off = 16; off > 0; off >>= 1)
            s = __fadd_rn(s, __shfl_xor_sync(0xffffffffu, s, off));
        if (t == 0) { g_c[j] = s; g_hist[j] = 0; }
    }
}

// exact dot chain, bit-identical to R6 (sequential ascending-k fmaf)
__device__ __forceinline__ float exact_metric(const float4* xr4, int code,
                                              float c, float sx) {
    const float4* er4 = (const float4*)(g_embn + code * DD);
    float acc = 0.0f;
#pragma unroll 8
    for (int q = 0; q < 64; q++) {
        float4 a = xr4[q], e = er4[q];
        acc = fmaf(a.x, e.x, acc);
        acc = fmaf(a.y, e.y, acc);
        acc = fmaf(a.z, e.z, acc);
        acc = fmaf(a.w, e.w, acc);
    }
    return __fadd_rn(__fadd_rn(c, sx), -2.0f * acc);
}

// ---------------------------------------------------------------------------
// Main: 128 rows x 512 codes per CTA, single-pass bf16 mma + guarded rescore
// ---------------------------------------------------------------------------
__global__ void __launch_bounds__(256, 2)
vq_main_kernel(const float* __restrict__ x,
               const float* __restrict__ emb,
               float* __restrict__ out) {
    extern __shared__ char smem[];
    const uint32_t sb = smem_u32(smem);
    const int tid = threadIdx.x;
    const int wid = tid >> 5;
    const int lid = tid & 31;
    const long r0 = (long)blockIdx.x * MT;

    float* c_s   = (float*)(smem + SM_CS);
    float* sx_s  = (float*)(smem + SM_SX);
    float* m1_s  = (float*)(smem + SM_M1);
    int*   i1_s  = (int*)(smem + SM_I1);
    float* m2_s  = (float*)(smem + SM_M2);
    int*   i2_s  = (int*)(smem + SM_I2);
    float* m3_s  = (float*)(smem + SM_M3);
    int*   rid_s = (int*)(smem + SM_RID);
    int*   flgA  = (int*)(smem + SM_FLGA);
    int*   flgB  = (int*)(smem + SM_FLGB);
    int*   ixb1  = (int*)(smem + SM_IXB1);
    int*   ixb2  = (int*)(smem + SM_IXB2);
    int*   cnt_s = (int*)(smem + SM_CNT);
    float* lred  = (float*)(smem + SM_LRED);

    const float4* xg4 = (const float4*)(x + r0 * DD);   // 64 float4 per row

    // c_j
    for (int i = tid; i < MM; i += 256) c_s[i] = g_c[i];
    if (tid < 2) cnt_s[tid] = 0;

    // A fill (once): x -> bf16 hi (packed cvt), swizzled [row][256 bf16] pitch 512B
#pragma unroll
    for (int i = 0; i < 32; i++) {
        int v   = tid + i * 256;      // 8192 float4
        int row = v >> 6;
        int kq  = v & 63;
        float4 f = xg4[row * 64 + kq];
        __nv_bfloat162 b01 = __floats2bfloat162_rn(f.x, f.y);
        __nv_bfloat162 b23 = __floats2bfloat162_rn(f.z, f.w);
        uint2 st;
        st.x = *(uint32_t*)&b01;
        st.y = *(uint32_t*)&b23;
        uint32_t ofs = (uint32_t)(kq * 8) ^ ((uint32_t)(row & 7) * 16);
        *(uint2*)(smem + SM_A + row * 512 + ofs) = st;
    }

    // prefetch chunk 0 (ct=0, kc=0) into buf0 via cp.async
    {
#pragma unroll
        for (int i = 0; i < 4; i++) {
            int v = tid + i * 256;          // 1024 uint4
            int j = v >> 3, q = v & 7;
            const char* src = (const char*)g_ebH + ((long)j * DD + q * 8) * 2;
            uint32_t dst = sb + SM_B0 + j * 128 +
                           (((uint32_t)(q * 16)) ^ ((uint32_t)(j & 7) * 16));
            CP_ASYNC16(dst, src);
        }
        CP_COMMIT();
    }

    // lane-invariant ldmatrix address pieces (verified in R13/R14)
    const int arow = wid * 16 + (lid & 7) + (lid & 8);
    const uint32_t a_rowoff = (uint32_t)arow * 512;
    const uint32_t a_rowxor = (uint32_t)(arow & 7) * 16;
    const uint32_t a_coladd = (uint32_t)(lid & 16);
    const int      b_lrow   = (lid & 7) + ((lid & 16) >> 1);
    const uint32_t b_coladd = (uint32_t)(lid & 8) * 2;

    const int r_lo = wid * 16 + (lid >> 2);
    const int r_hi = r_lo + 8;

    Top3 t3[2];
#pragma unroll
    for (int s = 0; s < 2; s++) {
        t3[s].m1 = t3[s].m2 = t3[s].m3 = INFINITY;
        t3[s].i1 = t3[s].i2 = 0;
    }

    int cc = 0;
    for (int ct = 0; ct < 4; ct++) {
        float acc[16][4];
#pragma unroll
        for (int n = 0; n < 16; n++)
#pragma unroll
            for (int c = 0; c < 4; c++) acc[n][c] = 0.0f;

        for (int kc = 0; kc < 4; kc++) {
            CP_WAIT0();
            __syncthreads();                    // chunk cc visible to all

            if (cc < 15) {                      // prefetch next chunk
                int nct = (cc + 1) >> 2, nkc = (cc + 1) & 3;
                uint32_t nb = sb + (((cc + 1) & 1) ? SM_B1 : SM_B0);
#pragma unroll
                for (int i = 0; i < 4; i++) {
                    int v = tid + i * 256;
                    int j = v >> 3, q = v & 7;
                    const char* src = (const char*)g_ebH +
                        ((long)(nct * 128 + j) * DD + nkc * 64 + q * 8) * 2;
                    uint32_t dst = nb + j * 128 +
                        (((uint32_t)(q * 16)) ^ ((uint32_t)(j & 7) * 16));
                    CP_ASYNC16(dst, src);
                }
                CP_COMMIT();
            }

            const uint32_t bbase = sb + ((cc & 1) ? SM_B1 : SM_B0);
#pragma unroll
            for (int ks = 0; ks < 4; ks++) {
                uint32_t cbA = (uint32_t)(kc * 128 + ks * 32) + a_coladd;
                uint32_t ah[4];
                ldsm4(ah, sb + SM_A + a_rowoff + (cbA ^ a_rowxor));
                uint32_t cbB = (uint32_t)(ks * 32) + b_coladd;
#pragma unroll
                for (int nt2 = 0; nt2 < 8; nt2++) {
                    int code = nt2 * 16 + b_lrow;
                    uint32_t boff = (uint32_t)code * 128 +
                                    (cbB ^ ((uint32_t)(code & 7) * 16));
                    uint32_t bh[4];
                    ldsm4(bh, bbase + boff);
                    mma_bf16(acc[nt2 * 2],     ah, bh[0], bh[1]);
                    mma_bf16(acc[nt2 * 2 + 1], ah, bh[2], bh[3]);
                }
            }
            __syncthreads();                    // protect buffer for next prefetch
            cc++;
        }

        // fold this code tile into top-3. sx is a row-constant: it cancels in
        // all within-row comparisons, so the approx metric omits it entirely.
#pragma unroll
        for (int nt = 0; nt < 16; nt++) {
            int j0 = ct * 128 + nt * 8 + (lid & 3) * 2;
#pragma unroll
            for (int c = 0; c < 4; c++) {
                int slot = c >> 1;
                int j = j0 + (c & 1);
                float m = fmaf(-2.0f, acc[nt][c], c_s[j]);
                t3_ins(t3[slot], m, j);
            }
        }
    }

    // merge across the 4 lanes sharing each row (xor 1, 2)
#pragma unroll
    for (int s = 0; s < 2; s++) {
#pragma unroll
        for (int off = 1; off <= 2; off <<= 1) {
            float om1 = __shfl_xor_sync(0xffffffffu, t3[s].m1, off);
            int   oi1 = __shfl_xor_sync(0xffffffffu, t3[s].i1, off);
            float om2 = __shfl_xor_sync(0xffffffffu, t3[s].m2, off);
            int   oi2 = __shfl_xor_sync(0xffffffffu, t3[s].i2, off);
            float om3 = __shfl_xor_sync(0xffffffffu, t3[s].m3, off);
            t3_ins(t3[s], om1, oi1);
            t3_ins(t3[s], om2, oi2);
            if (om3 < t3[s].m3) t3[s].m3 = om3;
        }
    }
    if ((lid & 3) == 0) {
        m1_s[r_lo] = t3[0].m1; i1_s[r_lo] = t3[0].i1;
        m2_s[r_lo] = t3[0].m2; i2_s[r_lo] = t3[0].i2; m3_s[r_lo] = t3[0].m3;
        m1_s[r_hi] = t3[1].m1; i1_s[r_hi] = t3[1].i1;
        m2_s[r_hi] = t3[1].m2; i2_s[r_hi] = t3[1].i2; m3_s[r_hi] = t3[1].m3;
    }
    __syncthreads();

    // classify rows
    if (tid < MT) {
        int row = tid;
        rid_s[row] = i1_s[row];
        float lim = m1_s[row] + TAU;
        if (m3_s[row] <= lim) {                 // rare: full exact rescan
            int p = atomicAdd(&cnt_s[0], 1);
            flgA[p] = row;
        } else if (m2_s[row] <= lim) {          // pair rescore
            int p = atomicAdd(&cnt_s[1], 1);
            flgB[p] = row; ixb1[p] = i1_s[row]; ixb2[p] = i2_s[row];
        }
    }
    __syncthreads();

    // exact sx (bit-identical XLA order) for flagged rows only
    {
        int cA = cnt_s[0], tot = cA + cnt_s[1];
        for (int f = wid; f < tot; f += 8) {
            int row = (f < cA) ? flgA[f] : flgB[f - cA];
            float4 a  = xg4[row * 64 + lid];
            float4 bq = xg4[row * 64 + 32 + lid];
            float s = 0.0f;
            s = __fadd_rn(s, __fmul_rn(a.x, a.x));
            s = __fadd_rn(s, __fmul_rn(a.y, a.y));
            s = __fadd_rn(s, __fmul_rn(a.z, a.z));
            s = __fadd_rn(s, __fmul_rn(a.w, a.w));
            s = __fadd_rn(s, __fmul_rn(bq.x, bq.x));
            s = __fadd_rn(s, __fmul_rn(bq.y, bq.y));
            s = __fadd_rn(s, __fmul_rn(bq.z, bq.z));
            s = __fadd_rn(s, __fmul_rn(bq.w, bq.w));
#pragma unroll
            for (int off = 16; off > 0; off >>= 1)
                s = __fadd_rn(s, __shfl_xor_sync(0xffffffffu, s, off));
            if (lid == 0) sx_s[row] = s;
        }
    }
    __syncthreads();

    // pair rescores: warp 0, 16 pairs at a time (lane pairs)
    if (wid == 0) {
        int cntB = cnt_s[1];
        for (int base = 0; base < cntB; base += 16) {
            int e = base + (lid >> 1);
            bool act = e < cntB;
            int row = 0, code = 0;
            float me = INFINITY;
            if (act) {
                row  = flgB[e];
                code = (lid & 1) ? ixb2[e] : ixb1[e];
                me = exact_metric((const float4*)(x + (r0 + row) * DD),
                                  code, c_s[code], sx_s[row]);
            }
            float om = __shfl_xor_sync(0xffffffffu, me, 1);
            int   oc = __shfl_xor_sync(0xffffffffu, code, 1);
            if (act && !(lid & 1)) {
                rid_s[row] = (me < om || (me == om && code < oc)) ? code : oc;
            }
        }
    }
    // full rescans: warps 1..7
    if (wid >= 1) {
        int cntA = cnt_s[0];
        for (int f = wid - 1; f < cntA; f += 7) {
            int row = flgA[f];
            const float4* xr4 = (const float4*)(x + (r0 + row) * DD);
            float sx = sx_s[row];
            float bv = INFINITY; int bi = 0;
            for (int t = 0; t < 16; t++) {
                int j = t * 32 + lid;
                float me = exact_metric(xr4, j, c_s[j], sx);
                if (me < bv) { bv = me; bi = j; }
            }
#pragma unroll
            for (int off = 16; off > 0; off >>= 1) {
                float ov = __shfl_xor_sync(0xffffffffu, bv, off);
                int   oi = __shfl_xor_sync(0xffffffffu, bi, off);
                if (ov < bv || (ov == bv && oi < bi)) { bv = ov; bi = oi; }
            }
            if (lid == 0) rid_s[row] = bi;
        }
    }
    __syncthreads();

    if (tid < MT) atomicAdd(&g_hist[rid_s[tid]], 1);

    // gather + straight-through + loss, packed f32x2 (per-lane IEEE RN:
    // bit-identical to the scalar reference-order arithmetic)
    unsigned long long lacc = 0ull;
    {
        int r  = tid >> 1;
        int kb = (tid & 1) * 128;
        int idx = rid_s[r];
        const float4* eq = (const float4*)(emb + (long)idx * DD + kb);
        const float4* xq = (const float4*)(x + (r0 + r) * DD + kb);
        float4*       og = (float4*)(out + (r0 + r) * DD + kb);
#pragma unroll
        for (int i = 0; i < 32; i++) {
            F4U Q, X, O;
            Q.f = eq[i];
            X.f = xq[i];
#pragma unroll
            for (int h = 0; h < 2; h++) {
                unsigned long long nx = X.u[h] ^ SGN2;
                unsigned long long t1, t2, t3v;
                ADD2(t1, Q.u[h], nx);        // q - x
                ADD2(t2, X.u[h], t1);        // x + (q - x)
                ADD2(t3v, t2, Q.u[h]);       // + q
                MUL2(O.u[h], t3v, (unsigned long long)HALF2C);  // * 0.5
                unsigned long long nq = Q.u[h] ^ SGN2;
                unsigned long long d;
                ADD2(d, X.u[h], nq);         // x - q
                FMA2(lacc, d, d);
            }
            og[i] = O.f;
        }
    }
    float llo, lhi;
    UNPK2(llo, lhi, lacc);
    float lsum = llo + lhi;
#pragma unroll
    for (int off = 16; off > 0; off >>= 1)
        lsum += __shfl_down_sync(0xffffffffu, lsum, off);
    if (lid == 0) lred[wid] = lsum;
    __syncthreads();
    if (tid == 0) {
        float tot = 0.0f;
        for (int w = 0; w < 8; w++) tot += lred[w];
        g_loss_part[blockIdx.x] = tot;
    }
}

// ---------------------------------------------------------------------------
// Finalize: loss mean + perplexity. 1 block x 512 threads.
// ---------------------------------------------------------------------------
__global__ void vq_finalize_kernel(float* __restrict__ out, int write_scalars) {
    __shared__ float red[512];
    int t = threadIdx.x;

    red[t] = g_loss_part[t];
    __syncthreads();
#pragma unroll
    for (int st = 256; st > 0; st >>= 1) {
        if (t < st) red[t] += red[t + st];
        __syncthreads();
    }
    float loss = red[0] / (float)NTD;

    float p = (float)g_hist[t] * (1.0f / (float)NT);
    red[t] = p * logf(p + 1e-10f);
    __syncthreads();
#pragma unroll
    for (int st = 256; st > 0; st >>= 1) {
        if (t < st) red[t] += red[t + st];
        __syncthreads();
    }
    if (t == 0 && write_scalars) {
        out[NTD]     = loss;
        out[NTD + 1] = expf(-red[0]);
    }
}

// ---------------------------------------------------------------------------
extern "C" void kernel_launch(void* const* d_in, const int* in_sizes, int n_in,
                              void* d_out, int out_size) {
    const float* x   = (const float*)d_in[0];
    const float* emb = (const float*)d_in[1];
    float* out = (float*)d_out;

    cudaFuncSetAttribute(vq_main_kernel,
                         cudaFuncAttributeMaxDynamicSharedMemorySize, SMEM_TOTAL);

    vq_prep_kernel<<<MM, 256>>>(emb);
    vq_main_kernel<<<NB, 256, SMEM_TOTAL>>>(x, emb, out);
    int write_scalars = (out_size >= NTD + 2) ? 1 : 0;
    vq_finalize_kernel<<<1, 512>>>(out, write_scalars);
}

// round 16
// speedup vs baseline: 2.1016x; 1.0889x over previous
#include <cuda_runtime.h>
#include <cuda_bf16.h>
#include <math.h>
#include <stdint.h>

// Problem constants
#define NT    65536
#define DD    256
#define MM    512
#define NTD   16777216
#define MT    128                 // rows per score-CTA
#define NB    (NT / MT)           // 512 score CTAs
#define TAU   0.03f               // guard band ~8 sigma of bf16 hi-only error
#define GB    2048                // gather blocks (32 rows each)

// K1 smem byte offsets
#define SM_A     0                // A hi: 128 rows x 512B (256 bf16, full K)
#define SM_B0    65536            // B chunk buf0: 128 codes x 128B (64 bf16)
#define SM_B1    81920            // B chunk buf1
#define SM_CS    98304            // c_j [512] f32
#define SM_SX    100352           // sx [128] f32 (exact, flagged rows only)
#define SM_M1    100864           // [128] f32
#define SM_I1    101376           // [128] int
#define SM_M2    101888           // [128] f32
#define SM_I2    102400           // [128] int
#define SM_M3    102912           // [128] f32
#define SM_RID   103424           // [128] int
#define SM_FLGA  103936           // [128] rows needing full rescan
#define SM_FLGB  104448           // [128] rows needing pair rescore
#define SM_IXB1  104960           // [128] pair candidate 1
#define SM_IXB2  105472           // [128] pair candidate 2
#define SM_CNT   105984           // [2] int: cntA, cntB
#define SMEM_TOTAL 106048

// Device scratch
__device__ float         g_embn[MM * DD];   // normalized codebook [j][k] fp32
__device__ __nv_bfloat16 g_ebH[MM * DD];    // bf16 hi [j][k]
__device__ float         g_c[MM];
__device__ int           g_rid[NT];         // selected code per row
__device__ float         g_loss_part[GB];
__device__ int           g_hist[MM];

__device__ __forceinline__ uint32_t smem_u32(const void* p) {
    uint32_t a;
    asm("{ .reg .u64 t; cvta.to.shared.u64 t, %1; cvt.u32.u64 %0, t; }" : "=r"(a) : "l"(p));
    return a;
}
__device__ __forceinline__ void ldsm4(uint32_t* r, uint32_t addr) {
    asm volatile("ldmatrix.sync.aligned.m8n8.x4.shared.b16 {%0,%1,%2,%3}, [%4];"
        : "=r"(r[0]), "=r"(r[1]), "=r"(r[2]), "=r"(r[3]) : "r"(addr));
}
__device__ __forceinline__ void mma_bf16(float* d, const uint32_t* a,
                                         uint32_t b0, uint32_t b1) {
    asm volatile("mma.sync.aligned.m16n8k16.row.col.f32.bf16.bf16.f32 "
        "{%0,%1,%2,%3}, {%4,%5,%6,%7}, {%8,%9}, {%0,%1,%2,%3};"
        : "+f"(d[0]), "+f"(d[1]), "+f"(d[2]), "+f"(d[3])
        : "r"(a[0]), "r"(a[1]), "r"(a[2]), "r"(a[3]), "r"(b0), "r"(b1));
}
#define CP_ASYNC16(saddr, gptr) \
    asm volatile("cp.async.cg.shared.global [%0], [%1], 16;" :: "r"(saddr), "l"(gptr))
#define CP_COMMIT() asm volatile("cp.async.commit_group;" ::: "memory")
#define CP_WAIT0()  asm volatile("cp.async.wait_group 0;" ::: "memory")

// packed f32x2 (per-lane IEEE RN)
#define ADD2(d, a, b) asm("add.rn.f32x2 %0, %1, %2;" : "=l"(d) : "l"(a), "l"(b))
#define MUL2(d, a, b) asm("mul.rn.f32x2 %0, %1, %2;" : "=l"(d) : "l"(a), "l"(b))
#define FMA2(d, a, b) asm("fma.rn.f32x2 %0, %1, %2, %0;" : "+l"(d) : "l"(a), "l"(b))
#define UNPK2(lo, hi, v) asm("mov.b64 {%0,%1}, %2;" : "=f"(lo), "=f"(hi) : "l"(v))
#define SGN2 0x8000000080000000ull
#define HALF2C 0x3F0000003F000000ull

union F4U { float4 f; unsigned long long u[2]; };

// top-3 tracker (indices for top-2 only; m3 is a value bound)
struct Top3 { float m1, m2, m3; int i1, i2; };
__device__ __forceinline__ void t3_ins(Top3& t, float m, int i) {
    if (m < t.m1 || (m == t.m1 && i < t.i1)) {
        t.m3 = t.m2; t.m2 = t.m1; t.i2 = t.i1; t.m1 = m; t.i1 = i;
    } else if (m < t.m2 || (m == t.m2 && i < t.i2)) {
        t.m3 = t.m2; t.m2 = m; t.i2 = i;
    } else if (m < t.m3) t.m3 = m;
}

// ---------------------------------------------------------------------------
// Prep: normalize codebook, bf16 hi split, c_j, zero hist
// ---------------------------------------------------------------------------
__global__ void vq_prep_kernel(const float* __restrict__ emb) {
    int j = blockIdx.x;
    int t = threadIdx.x;
    __shared__ float sq[256];
    __shared__ float norm_s;

    float v = emb[j * DD + t];
    sq[t] = __fmul_rn(v, v);
    __syncthreads();
    if (t < 32) {
        float s = 0.0f;
#pragma unroll
        for (int c = 0; c < 4; c++) s = __fadd_rn(s, sq[4 * t + c]);
#pragma unroll
        for (int c = 0; c < 4; c++) s = __fadd_rn(s, sq[128 + 4 * t + c]);
#pragma unroll
        for (int off = 16; off > 0; off >>= 1)
            s = __fadd_rn(s, __shfl_xor_sync(0xffffffffu, s, off));
        if (t == 0) norm_s = sqrtf(s);
    }
    __syncthreads();

    float e = v / __fadd_rn(norm_s, 1e-4f);
    g_embn[j * DD + t] = e;
    g_ebH[j * DD + t] = __float2bfloat16(e);

    sq[t] = __fmul_rn(e, e);
    __syncthreads();
    if (t < 32) {
        float s = 0.0f;
#pragma unroll
        for (int c = 0; c < 4; c++) s = __fadd_rn(s, sq[4 * t + c]);
#pragma unroll
        for (int c = 0; c < 4; c++) s = __fadd_rn(s, sq[128 + 4 * t + c]);
#pragma unroll
        for (int off = 16; off > 0; off >>= 1)
            s = __fadd_rn(s, __shfl_xor_sync(0xffffffffu, s, off));
        if (t == 0) { g_c[j] = s; g_hist[j] = 0; }
    }
}

// exact dot chain, bit-identical to R6 (sequential ascending-k fmaf)
__device__ __forceinline__ float exact_metric(const float4* xr4, int code,
                                              float c, float sx) {
    const float4* er4 = (const float4*)(g_embn + code * DD);
    float acc = 0.0f;
#pragma unroll 8
    for (int q = 0; q < 64; q++) {
        float4 a = xr4[q], e = er4[q];
        acc = fmaf(a.x, e.x, acc);
        acc = fmaf(a.y, e.y, acc);
        acc = fmaf(a.z, e.z, acc);
        acc = fmaf(a.w, e.w, acc);
    }
    return __fadd_rn(__fadd_rn(c, sx), -2.0f * acc);
}

// ---------------------------------------------------------------------------
// K1: scores + guarded argmin -> g_rid, histogram. 512 CTAs x 256 thr.
// ---------------------------------------------------------------------------
__global__ void __launch_bounds__(256, 2)
vq_score_kernel(const float* __restrict__ x) {
    extern __shared__ char smem[];
    const uint32_t sb = smem_u32(smem);
    const int tid = threadIdx.x;
    const int wid = tid >> 5;
    const int lid = tid & 31;
    const long r0 = (long)blockIdx.x * MT;

    float* c_s   = (float*)(smem + SM_CS);
    float* sx_s  = (float*)(smem + SM_SX);
    float* m1_s  = (float*)(smem + SM_M1);
    int*   i1_s  = (int*)(smem + SM_I1);
    float* m2_s  = (float*)(smem + SM_M2);
    int*   i2_s  = (int*)(smem + SM_I2);
    float* m3_s  = (float*)(smem + SM_M3);
    int*   rid_s = (int*)(smem + SM_RID);
    int*   flgA  = (int*)(smem + SM_FLGA);
    int*   flgB  = (int*)(smem + SM_FLGB);
    int*   ixb1  = (int*)(smem + SM_IXB1);
    int*   ixb2  = (int*)(smem + SM_IXB2);
    int*   cnt_s = (int*)(smem + SM_CNT);

    const float4* xg4 = (const float4*)(x + r0 * DD);   // 64 float4 per row

    // c_j
    for (int i = tid; i < MM; i += 256) c_s[i] = g_c[i];
    if (tid < 2) cnt_s[tid] = 0;

    // A fill (once): x -> bf16 hi (packed cvt), swizzled [row][256 bf16] pitch 512B
#pragma unroll
    for (int i = 0; i < 32; i++) {
        int v   = tid + i * 256;      // 8192 float4
        int row = v >> 6;
        int kq  = v & 63;
        float4 f = xg4[row * 64 + kq];
        __nv_bfloat162 b01 = __floats2bfloat162_rn(f.x, f.y);
        __nv_bfloat162 b23 = __floats2bfloat162_rn(f.z, f.w);
        uint2 st;
        st.x = *(uint32_t*)&b01;
        st.y = *(uint32_t*)&b23;
        uint32_t ofs = (uint32_t)(kq * 8) ^ ((uint32_t)(row & 7) * 16);
        *(uint2*)(smem + SM_A + row * 512 + ofs) = st;
    }

    // prefetch chunk 0 into buf0
    {
#pragma unroll
        for (int i = 0; i < 4; i++) {
            int v = tid + i * 256;
            int j = v >> 3, q = v & 7;
            const char* src = (const char*)g_ebH + ((long)j * DD + q * 8) * 2;
            uint32_t dst = sb + SM_B0 + j * 128 +
                           (((uint32_t)(q * 16)) ^ ((uint32_t)(j & 7) * 16));
            CP_ASYNC16(dst, src);
        }
        CP_COMMIT();
    }

    // lane-invariant ldmatrix address pieces (proven R13-R15)
    const int arow = wid * 16 + (lid & 7) + (lid & 8);
    const uint32_t a_rowoff = (uint32_t)arow * 512;
    const uint32_t a_rowxor = (uint32_t)(arow & 7) * 16;
    const uint32_t a_coladd = (uint32_t)(lid & 16);
    const int      b_lrow   = (lid & 7) + ((lid & 16) >> 1);
    const uint32_t b_coladd = (uint32_t)(lid & 8) * 2;

    const int r_lo = wid * 16 + (lid >> 2);
    const int r_hi = r_lo + 8;

    Top3 t3[2];
#pragma unroll
    for (int s = 0; s < 2; s++) {
        t3[s].m1 = t3[s].m2 = t3[s].m3 = INFINITY;
        t3[s].i1 = t3[s].i2 = 0;
    }

    int cc = 0;
    for (int ct = 0; ct < 4; ct++) {
        float acc[16][4];
#pragma unroll
        for (int n = 0; n < 16; n++)
#pragma unroll
            for (int c = 0; c < 4; c++) acc[n][c] = 0.0f;

        for (int kc = 0; kc < 4; kc++) {
            // single barrier per chunk: at this sync all warps finished chunk
            // cc-1's mma, so prefetching cc+1 into buf (cc-1)&1 is safe.
            CP_WAIT0();
            __syncthreads();

            if (cc < 15) {
                int nct = (cc + 1) >> 2, nkc = (cc + 1) & 3;
                uint32_t nb = sb + (((cc + 1) & 1) ? SM_B1 : SM_B0);
#pragma unroll
                for (int i = 0; i < 4; i++) {
                    int v = tid + i * 256;
                    int j = v >> 3, q = v & 7;
                    const char* src = (const char*)g_ebH +
                        ((long)(nct * 128 + j) * DD + nkc * 64 + q * 8) * 2;
                    uint32_t dst = nb + j * 128 +
                        (((uint32_t)(q * 16)) ^ ((uint32_t)(j & 7) * 16));
                    CP_ASYNC16(dst, src);
                }
                CP_COMMIT();
            }

            const uint32_t bbase = sb + ((cc & 1) ? SM_B1 : SM_B0);
#pragma unroll
            for (int ks = 0; ks < 4; ks++) {
                uint32_t cbA = (uint32_t)(kc * 128 + ks * 32) + a_coladd;
                uint32_t ah[4];
                ldsm4(ah, sb + SM_A + a_rowoff + (cbA ^ a_rowxor));
                uint32_t cbB = (uint32_t)(ks * 32) + b_coladd;
#pragma unroll
                for (int nt2 = 0; nt2 < 8; nt2++) {
                    int code = nt2 * 16 + b_lrow;
                    uint32_t boff = (uint32_t)code * 128 +
                                    (cbB ^ ((uint32_t)(code & 7) * 16));
                    uint32_t bh[4];
                    ldsm4(bh, bbase + boff);
                    mma_bf16(acc[nt2 * 2],     ah, bh[0], bh[1]);
                    mma_bf16(acc[nt2 * 2 + 1], ah, bh[2], bh[3]);
                }
            }
            cc++;
        }

        // fold this code tile into top-3 (sx cancels within-row; omitted)
#pragma unroll
        for (int nt = 0; nt < 16; nt++) {
            int j0 = ct * 128 + nt * 8 + (lid & 3) * 2;
#pragma unroll
            for (int c = 0; c < 4; c++) {
                int slot = c >> 1;
                int j = j0 + (c & 1);
                float m = fmaf(-2.0f, acc[nt][c], c_s[j]);
                t3_ins(t3[slot], m, j);
            }
        }
    }

    // merge across the 4 lanes sharing each row (xor 1, 2)
#pragma unroll
    for (int s = 0; s < 2; s++) {
#pragma unroll
        for (int off = 1; off <= 2; off <<= 1) {
            float om1 = __shfl_xor_sync(0xffffffffu, t3[s].m1, off);
            int   oi1 = __shfl_xor_sync(0xffffffffu, t3[s].i1, off);
            float om2 = __shfl_xor_sync(0xffffffffu, t3[s].m2, off);
            int   oi2 = __shfl_xor_sync(0xffffffffu, t3[s].i2, off);
            float om3 = __shfl_xor_sync(0xffffffffu, t3[s].m3, off);
            t3_ins(t3[s], om1, oi1);
            t3_ins(t3[s], om2, oi2);
            if (om3 < t3[s].m3) t3[s].m3 = om3;
        }
    }
    __syncthreads();
    if ((lid & 3) == 0) {
        m1_s[r_lo] = t3[0].m1; i1_s[r_lo] = t3[0].i1;
        m2_s[r_lo] = t3[0].m2; i2_s[r_lo] = t3[0].i2; m3_s[r_lo] = t3[0].m3;
        m1_s[r_hi] = t3[1].m1; i1_s[r_hi] = t3[1].i1;
        m2_s[r_hi] = t3[1].m2; i2_s[r_hi] = t3[1].i2; m3_s[r_hi] = t3[1].m3;
    }
    __syncthreads();

    // classify rows
    if (tid < MT) {
        int row = tid;
        rid_s[row] = i1_s[row];
        float lim = m1_s[row] + TAU;
        if (m3_s[row] <= lim) {                 // rare: full exact rescan
            int p = atomicAdd(&cnt_s[0], 1);
            flgA[p] = row;
        } else if (m2_s[row] <= lim) {          // pair rescore
            int p = atomicAdd(&cnt_s[1], 1);
            flgB[p] = row; ixb1[p] = i1_s[row]; ixb2[p] = i2_s[row];
        }
    }
    __syncthreads();

    // exact sx (bit-identical XLA order) for flagged rows only
    {
        int cA = cnt_s[0], tot = cA + cnt_s[1];
        for (int f = wid; f < tot; f += 8) {
            int row = (f < cA) ? flgA[f] : flgB[f - cA];
            float4 a  = xg4[row * 64 + lid];
            float4 bq = xg4[row * 64 + 32 + lid];
            float s = 0.0f;
            s = __fadd_rn(s, __fmul_rn(a.x, a.x));
            s = __fadd_rn(s, __fmul_rn(a.y, a.y));
            s = __fadd_rn(s, __fmul_rn(a.z, a.z));
            s = __fadd_rn(s, __fmul_rn(a.w, a.w));
            s = __fadd_rn(s, __fmul_rn(bq.x, bq.x));
            s = __fadd_rn(s, __fmul_rn(bq.y, bq.y));
            s = __fadd_rn(s, __fmul_rn(bq.z, bq.z));
            s = __fadd_rn(s, __fmul_rn(bq.w, bq.w));
#pragma unroll
            for (int off = 16; off > 0; off >>= 1)
                s = __fadd_rn(s, __shfl_xor_sync(0xffffffffu, s, off));
            if (lid == 0) sx_s[row] = s;
        }
    }
    __syncthreads();

    // pair rescores: warp 0, 16 pairs at a time (lane pairs)
    if (wid == 0) {
        int cntB = cnt_s[1];
        for (int base = 0; base < cntB; base += 16) {
            int e = base + (lid >> 1);
            bool act = e < cntB;
            int row = 0, code = 0;
            float me = INFINITY;
            if (act) {
                row  = flgB[e];
                code = (lid & 1) ? ixb2[e] : ixb1[e];
                me = exact_metric((const float4*)(x + (r0 + row) * DD),
                                  code, c_s[code], sx_s[row]);
            }
            float om = __shfl_xor_sync(0xffffffffu, me, 1);
            int   oc = __shfl_xor_sync(0xffffffffu, code, 1);
            if (act && !(lid & 1)) {
                rid_s[row] = (me < om || (me == om && code < oc)) ? code : oc;
            }
        }
    }
    // full rescans: warps 1..7
    if (wid >= 1) {
        int cntA = cnt_s[0];
        for (int f = wid - 1; f < cntA; f += 7) {
            int row = flgA[f];
            const float4* xr4 = (const float4*)(x + (r0 + row) * DD);
            float sx = sx_s[row];
            float bv = INFINITY; int bi = 0;
            for (int t = 0; t < 16; t++) {
                int j = t * 32 + lid;
                float me = exact_metric(xr4, j, c_s[j], sx);
                if (me < bv) { bv = me; bi = j; }
            }
#pragma unroll
            for (int off = 16; off > 0; off >>= 1) {
                float ov = __shfl_xor_sync(0xffffffffu, bv, off);
                int   oi = __shfl_xor_sync(0xffffffffu, bi, off);
                if (ov < bv || (ov == bv && oi < bi)) { bv = ov; bi = oi; }
            }
            if (lid == 0) rid_s[row] = bi;
        }
    }
    __syncthreads();

    if (tid < MT) {
        int idx = rid_s[tid];
        g_rid[r0 + tid] = idx;
        atomicAdd(&g_hist[idx], 1);
    }
}

// ---------------------------------------------------------------------------
// K2: gather + straight-through + loss. 2048 blocks x 256 thr (32 rows each).
// Output arithmetic bit-identical to the passing R15 packed-f32x2 epilogue.
// ---------------------------------------------------------------------------
__global__ void __launch_bounds__(256)
vq_gather_kernel(const float* __restrict__ x,
                 const float* __restrict__ emb,
                 float* __restrict__ out) {
    __shared__ float lred[8];
    const int tid = threadIdx.x;
    const int wid = tid >> 5;
    const int lid = tid & 31;
    const long row = (long)blockIdx.x * 32 + (tid >> 3);
    const int  kb  = (tid & 7) * 32;          // floats

    int idx = g_rid[row];
    const float4* eq = (const float4*)(emb + (long)idx * DD + kb);
    const float4* xq = (const float4*)(x + row * DD + kb);
    float4*       og = (float4*)(out + row * DD + kb);

    unsigned long long lacc = 0ull;
#pragma unroll
    for (int i = 0; i < 8; i++) {
        F4U Q, X, O;
        Q.f = eq[i];
        X.f = xq[i];
#pragma unroll
        for (int h = 0; h < 2; h++) {
            unsigned long long nx = X.u[h] ^ SGN2;
            unsigned long long t1, t2, t3v;
            ADD2(t1, Q.u[h], nx);        // q - x
            ADD2(t2, X.u[h], t1);        // x + (q - x)
            ADD2(t3v, t2, Q.u[h]);       // + q
            MUL2(O.u[h], t3v, (unsigned long long)HALF2C);  // * 0.5
            unsigned long long nq = Q.u[h] ^ SGN2;
            unsigned long long d;
            ADD2(d, X.u[h], nq);         // x - q
            FMA2(lacc, d, d);
        }
        og[i] = O.f;
    }
    float llo, lhi;
    UNPK2(llo, lhi, lacc);
    float lsum = llo + lhi;
#pragma unroll
    for (int off = 16; off > 0; off >>= 1)
        lsum += __shfl_down_sync(0xffffffffu, lsum, off);
    if (lid == 0) lred[wid] = lsum;
    __syncthreads();
    if (tid == 0) {
        float tot = 0.0f;
        for (int w = 0; w < 8; w++) tot += lred[w];
        g_loss_part[blockIdx.x] = tot;
    }
}

// ---------------------------------------------------------------------------
// Finalize: loss mean + perplexity. 1 block x 512 threads.
// ---------------------------------------------------------------------------
__global__ void vq_finalize_kernel(float* __restrict__ out, int write_scalars) {
    __shared__ float red[512];
    int t = threadIdx.x;

    float s = 0.0f;
#pragma unroll
    for (int q = 0; q < 4; q++) s += g_loss_part[t + q * 512];
    red[t] = s;
    __syncthreads();
#pragma unroll
    for (int st = 256; st > 0; st >>= 1) {
        if (t < st) red[t] += red[t + st];
        __syncthreads();
    }
    float loss = red[0] / (float)NTD;

    float p = (float)g_hist[t] * (1.0f / (float)NT);
    red[t] = p * logf(p + 1e-10f);
    __syncthreads();
#pragma unroll
    for (int st = 256; st > 0; st >>= 1) {
        if (t < st) red[t] += red[t + st];
        __syncthreads();
    }
    if (t == 0 && write_scalars) {
        out[NTD]     = loss;
        out[NTD + 1] = expf(-red[0]);
    }
}

// ---------------------------------------------------------------------------
extern "C" void kernel_launch(void* const* d_in, const int* in_sizes, int n_in,
                              void* d_out, int out_size) {
    const float* x   = (const float*)d_in[0];
    const float* emb = (const float*)d_in[1];
    float* out = (float*)d_out;

    cudaFuncSetAttribute(vq_score_kernel,
                         cudaFuncAttributeMaxDynamicSharedMemorySize, SMEM_TOTAL);

    vq_prep_kernel<<<MM, 256>>>(emb);
    vq_score_kernel<<<NB, 256, SMEM_TOTAL>>>(x);
    vq_gather_kernel<<<GB, 256>>>(x, emb, out);
    int write_scalars = (out_size >= NTD + 2) ? 1 : 0;
    vq_finalize_kernel<<<1, 512>>>(out, write_scalars);
}